// round 1
// baseline (speedup 1.0000x reference)
#include <cuda_runtime.h>
#include <math.h>

// Problem constants
#define B_   2
#define S_   8192
#define C_   1536
#define P_   512
#define H_   32
#define F_   128
#define HF   4096      // H_ * F_
#define P2   1024      // 2 * P_

// ---------------- scratch (device globals; no cudaMalloc allowed) -------------
__device__ float g_xn [B_ * P_ * C_];
__device__ float g_xg [B_ * P_ * C_];
__device__ float g_q  [B_ * P_ * HF];
__device__ float g_k  [B_ * P_ * HF];
__device__ float g_pos[P2 * HF];
__device__ float g_yq [B_ * P_ * F_];
__device__ float g_yk [B_ * P_ * F_];
__device__ float g_QK [(size_t)B_ * H_ * P_ * P_];   //  67 MB  [b][h][q][k]
__device__ float g_Qp [(size_t)B_ * H_ * P_ * P2];   // 134 MB  [b][h][q][d]
__device__ float g_Kp [(size_t)B_ * H_ * P_ * P2];   // 134 MB  [b][h][k][d]

// ---------------- kernel 1: window-mean pool + RMS norm + exact GELU ----------
__global__ __launch_bounds__(256) void pool_norm_kernel(
    const float* __restrict__ x, const float* __restrict__ norm_w)
{
    int bid = blockIdx.x;            // 0..1023 = b*512 + p
    int b = bid >> 9, p = bid & 511;
    int tid = threadIdx.x;           // 256 threads, 6 channels each

    const float* xrow = x + ((size_t)b * S_ + (size_t)p * 16) * C_;

    float xp[6];
#pragma unroll
    for (int j = 0; j < 6; j++) xp[j] = 0.f;
    for (int r = 0; r < 16; r++) {
        const float* xr = xrow + (size_t)r * C_;
#pragma unroll
        for (int j = 0; j < 6; j++) xp[j] += xr[tid + j * 256];
    }
    float ssq = 0.f;
#pragma unroll
    for (int j = 0; j < 6; j++) { xp[j] *= (1.f / 16.f); ssq += xp[j] * xp[j]; }

    __shared__ float red[256];
    red[tid] = ssq;
    __syncthreads();
    for (int s = 128; s > 0; s >>= 1) {
        if (tid < s) red[tid] += red[tid + s];
        __syncthreads();
    }
    float scale = 1.f / sqrtf(red[0] * (1.f / (float)C_) + 1e-8f);

    float* xn_out = g_xn + (size_t)bid * C_;
    float* xg_out = g_xg + (size_t)bid * C_;
#pragma unroll
    for (int j = 0; j < 6; j++) {
        int ch = tid + j * 256;
        float v = xp[j] * scale * norm_w[ch];
        xn_out[ch] = v;
        // exact gelu: x * 0.5 * (1 + erf(x / sqrt(2)))
        xg_out[ch] = v * 0.5f * (1.f + erff(v * 0.70710678118654752f));
    }
}

// ---------------- kernel 2: central-mask features @ Wpos + bpos ---------------
__global__ __launch_bounds__(128) void pos_kernel(
    const float* __restrict__ Wpos, const float* __restrict__ bpos)
{
    int d   = blockIdx.x;            // 0..1023, rel = d - 512
    int tid = threadIdx.x;           // 128
    __shared__ float feat[32];

    int rel = d - P_;
    if (tid < 16) {
        // geomspace(1, 497, 16, endpoint=False) = exp(i * log(497)/16) (f64 -> f32)
        double geo = exp((double)tid * (log(497.0) / 16.0));
        float center = (float)tid + (float)geo;       // widths_lin + widths_geo (f32 add)
        float oh = (center > fabsf((float)rel)) ? 1.f : 0.f;
        float sg = (rel > 0) ? 1.f : ((rel < 0) ? -1.f : 0.f);
        feat[tid]      = oh;
        feat[tid + 16] = oh * sg;
    }
    __syncthreads();

    float f[32];
#pragma unroll
    for (int c = 0; c < 32; c++) f[c] = feat[c];

    for (int n = tid; n < HF; n += 128) {
        float acc = bpos[n];
#pragma unroll
        for (int c = 0; c < 32; c++) acc += f[c] * Wpos[c * HF + n];
        g_pos[(size_t)d * HF + n] = acc;
    }
}

// ---------------- kernel 3: SGEMM NN  (C[M,N] = A[M,K] @ B[K,N]) ---------------
// BM=BN=128, BK=16, 256 threads, 8x8 microtile
__global__ __launch_bounds__(256) void nn_gemm_kernel(
    const float* __restrict__ A, const float* __restrict__ Bm,
    float* __restrict__ C, int M, int N, int K)
{
    __shared__ float As[16][132];   // transposed, padded
    __shared__ float Bs[16][128];

    int tid = threadIdx.x;
    int ar  = tid >> 2;      // 0..63
    int ac4 = tid & 3;       // 0..3   -> cols ac4*4..+3
    int br  = tid >> 5;      // 0..7
    int bc4 = tid & 31;      // 0..31  -> cols bc4*4..+3
    int ty  = tid >> 4, tx = tid & 15;

    int rowA0 = blockIdx.y * 128;
    int colB0 = blockIdx.x * 128;

    float acc[8][8];
#pragma unroll
    for (int i = 0; i < 8; i++)
#pragma unroll
        for (int j = 0; j < 8; j++) acc[i][j] = 0.f;

    for (int k0 = 0; k0 < K; k0 += 16) {
#pragma unroll
        for (int i = 0; i < 2; i++) {
            int r = ar + i * 64;
            float4 va = *(const float4*)(A + (size_t)(rowA0 + r) * K + k0 + ac4 * 4);
            As[ac4 * 4 + 0][r] = va.x;
            As[ac4 * 4 + 1][r] = va.y;
            As[ac4 * 4 + 2][r] = va.z;
            As[ac4 * 4 + 3][r] = va.w;
        }
#pragma unroll
        for (int i = 0; i < 2; i++) {
            int r = br + i * 8;
            *(float4*)&Bs[r][bc4 * 4] =
                *(const float4*)(Bm + (size_t)(k0 + r) * N + colB0 + bc4 * 4);
        }
        __syncthreads();
#pragma unroll
        for (int kk = 0; kk < 16; kk++) {
            float4 a0 = *(const float4*)&As[kk][ty * 8];
            float4 a1 = *(const float4*)&As[kk][ty * 8 + 4];
            float4 b0 = *(const float4*)&Bs[kk][tx * 8];
            float4 b1 = *(const float4*)&Bs[kk][tx * 8 + 4];
            float arr[8] = {a0.x, a0.y, a0.z, a0.w, a1.x, a1.y, a1.z, a1.w};
            float brr[8] = {b0.x, b0.y, b0.z, b0.w, b1.x, b1.y, b1.z, b1.w};
#pragma unroll
            for (int i = 0; i < 8; i++)
#pragma unroll
                for (int j = 0; j < 8; j++) acc[i][j] += arr[i] * brr[j];
        }
        __syncthreads();
    }

#pragma unroll
    for (int i = 0; i < 8; i++) {
        float* crow = C + (size_t)(rowA0 + ty * 8 + i) * N + colB0 + tx * 8;
        *(float4*)crow       = make_float4(acc[i][0], acc[i][1], acc[i][2], acc[i][3]);
        *(float4*)(crow + 4) = make_float4(acc[i][4], acc[i][5], acc[i][6], acc[i][7]);
    }
}

// ---------------- kernel 4: batched SGEMM NT, K=128, per (b,h) slice ----------
// C[z][M][N] = alpha * (A+rowbias)[M,128] @ B[N,128]^T, lda=ldb=HF (head slices)
__global__ __launch_bounds__(256) void nt_gemm_kernel(
    const float* __restrict__ Abase, const float* __restrict__ Bbase,
    float* __restrict__ Cbase, const float* __restrict__ rowbias,
    int M, int N, int bInB, float alpha)
{
    int z = blockIdx.z;
    int b = z >> 5, h = z & 31;
    const float* A  = Abase + (size_t)b * P_ * HF + h * F_;
    const float* Bm = Bbase + (bInB ? (size_t)b * P_ * HF : 0) + h * F_;
    float* C = Cbase + (size_t)z * M * N;
    const float* bias = rowbias ? (rowbias + h * F_) : (const float*)0;

    __shared__ float As[32][132];
    __shared__ float Bs[32][132];

    int tid = threadIdx.x;
    int lr  = tid >> 3;   // 0..31
    int lc4 = tid & 7;    // 0..7  -> cols lc4*4..+3
    int ty  = tid >> 4, tx = tid & 15;

    int rowA0 = blockIdx.y * 128;
    int rowB0 = blockIdx.x * 128;

    float acc[8][8];
#pragma unroll
    for (int i = 0; i < 8; i++)
#pragma unroll
        for (int j = 0; j < 8; j++) acc[i][j] = 0.f;

    for (int k0 = 0; k0 < 128; k0 += 32) {
#pragma unroll
        for (int i = 0; i < 4; i++) {
            int r = lr + i * 32;
            float4 va = *(const float4*)(A + (size_t)(rowA0 + r) * HF + k0 + lc4 * 4);
            if (bias) {
                va.x += bias[k0 + lc4 * 4 + 0];
                va.y += bias[k0 + lc4 * 4 + 1];
                va.z += bias[k0 + lc4 * 4 + 2];
                va.w += bias[k0 + lc4 * 4 + 3];
            }
            As[lc4 * 4 + 0][r] = va.x;
            As[lc4 * 4 + 1][r] = va.y;
            As[lc4 * 4 + 2][r] = va.z;
            As[lc4 * 4 + 3][r] = va.w;
            float4 vb = *(const float4*)(Bm + (size_t)(rowB0 + r) * HF + k0 + lc4 * 4);
            Bs[lc4 * 4 + 0][r] = vb.x;
            Bs[lc4 * 4 + 1][r] = vb.y;
            Bs[lc4 * 4 + 2][r] = vb.z;
            Bs[lc4 * 4 + 3][r] = vb.w;
        }
        __syncthreads();
#pragma unroll
        for (int kk = 0; kk < 32; kk++) {
            float4 a0 = *(const float4*)&As[kk][ty * 8];
            float4 a1 = *(const float4*)&As[kk][ty * 8 + 4];
            float4 b0 = *(const float4*)&Bs[kk][tx * 8];
            float4 b1 = *(const float4*)&Bs[kk][tx * 8 + 4];
            float arr[8] = {a0.x, a0.y, a0.z, a0.w, a1.x, a1.y, a1.z, a1.w};
            float brr[8] = {b0.x, b0.y, b0.z, b0.w, b1.x, b1.y, b1.z, b1.w};
#pragma unroll
            for (int i = 0; i < 8; i++)
#pragma unroll
                for (int j = 0; j < 8; j++) acc[i][j] += arr[i] * brr[j];
        }
        __syncthreads();
    }

#pragma unroll
    for (int i = 0; i < 8; i++) {
        float* crow = C + (size_t)(rowA0 + ty * 8 + i) * N + rowB0 + tx * 8;
#pragma unroll
        for (int j = 0; j < 8; j++) crow[j] = acc[i][j] * alpha;
    }
}

// ---------------- kernel 5: fused gather + a@Wout epilogue --------------------
// CTA = (b, 32 q's, 32 k's). smem a[q][k][h] with conflict-free skewed strides.
#define A_QSTRIDE 1057   // 32*33 + 1
#define A_KSTRIDE 33
#define SMEM_FINAL ((32 * A_QSTRIDE + 2 * 32 * 128) * 4)

__global__ __launch_bounds__(256) void final_kernel(
    const float* __restrict__ QK, const float* __restrict__ Qp,
    const float* __restrict__ Kp,
    const float* __restrict__ yq, const float* __restrict__ yk,
    const float* __restrict__ Wout, const float* __restrict__ bout,
    float* __restrict__ out)
{
    extern __shared__ float smem[];
    float* a_s  = smem;                      // 32*1057
    float* yq_s = smem + 32 * A_QSTRIDE;     // 32*128
    float* yk_s = yq_s + 32 * 128;           // 32*128

    int b  = blockIdx.z;
    int qt = blockIdx.y * 32;
    int kt = blockIdx.x * 32;
    int tid = threadIdx.x;

    // stage yq / yk tiles
    for (int i = tid; i < 32 * 128; i += 256) {
        int q = i >> 7, f = i & 127;
        yq_s[i] = yq[((size_t)(b * P_) + qt + q) * F_ + f];
        yk_s[i] = yk[((size_t)(b * P_) + kt + q) * F_ + f];
    }

    // phase 1: a = QK + Qp   (k innermost -> coalesced, both sources contiguous in k)
    for (int i = tid; i < 32 * 32 * 32; i += 256) {
        int h = i >> 10, q = (i >> 5) & 31, k = i & 31;
        int gq = qt + q, gk = kt + k;
        size_t zb = (size_t)(b * 32 + h);
        float v = QK[(zb * P_ + gq) * P_ + gk]
                + Qp[(zb * P_ + gq) * P2 + (P_ + gk - gq)];
        a_s[q * A_QSTRIDE + k * A_KSTRIDE + h] = v;
    }
    __syncthreads();

    // phase 2: a += Kp   (q innermost -> Kp contiguous in q)
    for (int i = tid; i < 32 * 32 * 32; i += 256) {
        int h = i >> 10, k = (i >> 5) & 31, q = i & 31;
        int gq = qt + q, gk = kt + k;
        size_t zb = (size_t)(b * 32 + h);
        a_s[q * A_QSTRIDE + k * A_KSTRIDE + h] +=
            Kp[(zb * P_ + gk) * P2 + (P_ + gq - gk)];
    }
    __syncthreads();

    // epilogue: out[f] = bout + yq + yk + sum_h a_h * Wout[h][f]
    int lane = tid & 31, warp = tid >> 5;
    float w[32][4];
#pragma unroll
    for (int h = 0; h < 32; h++)
#pragma unroll
        for (int j = 0; j < 4; j++) w[h][j] = Wout[h * F_ + lane + j * 32];
    float bo[4];
#pragma unroll
    for (int j = 0; j < 4; j++) bo[j] = bout[lane + j * 32];

    for (int p = warp; p < 1024; p += 8) {
        int q = p >> 5, k = p & 31;
        const float* ap = a_s + q * A_QSTRIDE + k * A_KSTRIDE;
        float acc[4];
#pragma unroll
        for (int j = 0; j < 4; j++)
            acc[j] = bo[j] + yq_s[q * 128 + lane + j * 32]
                           + yk_s[k * 128 + lane + j * 32];
#pragma unroll
        for (int h = 0; h < 32; h++) {
            float ah = ap[h];
#pragma unroll
            for (int j = 0; j < 4; j++) acc[j] += ah * w[h][j];
        }
        float* orow = out + (((size_t)(b * P_) + qt + q) * P_ + kt + k) * F_ + lane;
#pragma unroll
        for (int j = 0; j < 4; j++) orow[j * 32] = acc[j];
    }
}

// ---------------- launch ------------------------------------------------------
extern "C" void kernel_launch(void* const* d_in, const int* in_sizes, int n_in,
                              void* d_out, int out_size)
{
    const float* x        = (const float*)d_in[0];
    const float* norm_w   = (const float*)d_in[1];
    const float* Wq       = (const float*)d_in[2];
    const float* Wk       = (const float*)d_in[3];
    const float* Wpos     = (const float*)d_in[4];
    const float* bpos     = (const float*)d_in[5];
    const float* q_r_bias = (const float*)d_in[6];
    const float* k_r_bias = (const float*)d_in[7];
    const float* Wyq      = (const float*)d_in[8];
    const float* Wyk      = (const float*)d_in[9];
    const float* Wout     = (const float*)d_in[10];
    const float* bout     = (const float*)d_in[11];
    float* out = (float*)d_out;

    float *p_xn, *p_xg, *p_q, *p_k, *p_pos, *p_yq, *p_yk, *p_QK, *p_Qp, *p_Kp;
    cudaGetSymbolAddress((void**)&p_xn,  g_xn);
    cudaGetSymbolAddress((void**)&p_xg,  g_xg);
    cudaGetSymbolAddress((void**)&p_q,   g_q);
    cudaGetSymbolAddress((void**)&p_k,   g_k);
    cudaGetSymbolAddress((void**)&p_pos, g_pos);
    cudaGetSymbolAddress((void**)&p_yq,  g_yq);
    cudaGetSymbolAddress((void**)&p_yk,  g_yk);
    cudaGetSymbolAddress((void**)&p_QK,  g_QK);
    cudaGetSymbolAddress((void**)&p_Qp,  g_Qp);
    cudaGetSymbolAddress((void**)&p_Kp,  g_Kp);

    pool_norm_kernel<<<1024, 256>>>(x, norm_w);
    pos_kernel<<<1024, 128>>>(Wpos, bpos);

    // projections: q = xn@Wq, k = xn@Wk, yq = gelu(xn)@Wyq, yk = gelu(xn)@Wyk
    nn_gemm_kernel<<<dim3(HF / 128, 8), 256>>>(p_xn, Wq,  p_q,  1024, HF,  C_);
    nn_gemm_kernel<<<dim3(HF / 128, 8), 256>>>(p_xn, Wk,  p_k,  1024, HF,  C_);
    nn_gemm_kernel<<<dim3(1, 8),        256>>>(p_xg, Wyq, p_yq, 1024, 128, C_);
    nn_gemm_kernel<<<dim3(1, 8),        256>>>(p_xg, Wyk, p_yk, 1024, 128, C_);

    // QK[b,h,q,k]; Qp[b,h,q,d] = 0.25*(q+qb)·pos; Kp[b,h,k,d] = 0.25*(k+kb)·pos
    nt_gemm_kernel<<<dim3(4, 4, 64), 256>>>(p_q, p_k,   p_QK, (const float*)0, P_, P_, 1, 1.0f);
    nt_gemm_kernel<<<dim3(8, 4, 64), 256>>>(p_q, p_pos, p_Qp, q_r_bias,        P_, P2, 0, 0.25f);
    nt_gemm_kernel<<<dim3(8, 4, 64), 256>>>(p_k, p_pos, p_Kp, k_r_bias,        P_, P2, 0, 0.25f);

    cudaFuncSetAttribute(final_kernel,
                         cudaFuncAttributeMaxDynamicSharedMemorySize, SMEM_FINAL);
    final_kernel<<<dim3(16, 16, 2), 256, SMEM_FINAL>>>(
        p_QK, p_Qp, p_Kp, p_yq, p_yk, Wout, bout, out);
}

// round 2
// speedup vs baseline: 1.1225x; 1.1225x over previous
#include <cuda_runtime.h>
#include <cuda_bf16.h>
#include <math.h>
#include <stdint.h>

// Problem constants
#define B_   2
#define S_   8192
#define C_   1536
#define P_   512
#define H_   32
#define F_   128
#define HF   4096      // H_ * F_
#define P2   1024      // 2 * P_

// ---------------- scratch (device globals; no cudaMalloc allowed) -------------
__device__ float g_xn [B_ * P_ * C_];
__device__ float g_xg [B_ * P_ * C_];
__device__ float g_q  [B_ * P_ * HF];
__device__ float g_k  [B_ * P_ * HF];
__device__ float g_pos[P2 * HF];
__device__ float g_yq [B_ * P_ * F_];
__device__ float g_yk [B_ * P_ * F_];
__device__ float g_QK [(size_t)B_ * H_ * P_ * P_];   //  67 MB  [b][h][q][k]
__device__ float g_Qp [(size_t)B_ * H_ * P_ * P2];   // 134 MB  [b][h][q][d]
__device__ float g_Kp [(size_t)B_ * H_ * P_ * P2];   // 134 MB  [b][h][k][d]

// ---------------- helpers ------------------------------------------------------
__device__ __forceinline__ void split2(float x, float y, uint32_t& hw, uint32_t& lw)
{
    __nv_bfloat16 hx = __float2bfloat16(x);
    __nv_bfloat16 hy = __float2bfloat16(y);
    __nv_bfloat16 lx = __float2bfloat16(x - __bfloat162float(hx));
    __nv_bfloat16 ly = __float2bfloat16(y - __bfloat162float(hy));
    __nv_bfloat162 hp = __halves2bfloat162(hx, hy);   // .x in low 16 bits
    __nv_bfloat162 lp = __halves2bfloat162(lx, ly);
    hw = *reinterpret_cast<uint32_t*>(&hp);
    lw = *reinterpret_cast<uint32_t*>(&lp);
}

#define MMA_BF16(c, a, b)                                                       \
    asm volatile(                                                               \
        "mma.sync.aligned.m16n8k16.row.col.f32.bf16.bf16.f32 "                  \
        "{%0,%1,%2,%3}, {%4,%5,%6,%7}, {%8,%9}, {%0,%1,%2,%3};\n"               \
        : "+f"((c)[0]), "+f"((c)[1]), "+f"((c)[2]), "+f"((c)[3])                \
        : "r"((a)[0]), "r"((a)[1]), "r"((a)[2]), "r"((a)[3]),                   \
          "r"((b)[0]), "r"((b)[1]))

// shared compute step for one k16 sub-step (expects smem arrays + indices)
#define FRAG_COMPUTE(AsH, AsL, BsH, BsL, j0)                                    \
    do {                                                                        \
        uint32_t ah[2][4], al[2][4], bh[8][2], bl[8][2];                        \
        _Pragma("unroll")                                                       \
        for (int mt = 0; mt < 2; mt++) {                                        \
            int rb = (m0 + mt * 16 + g) * 20 + (j0) + tig;                      \
            ah[mt][0] = AsH[rb];       ah[mt][1] = AsH[rb + 160];               \
            ah[mt][2] = AsH[rb + 4];   ah[mt][3] = AsH[rb + 164];               \
            al[mt][0] = AsL[rb];       al[mt][1] = AsL[rb + 160];               \
            al[mt][2] = AsL[rb + 4];   al[mt][3] = AsL[rb + 164];               \
        }                                                                       \
        _Pragma("unroll")                                                       \
        for (int nt = 0; nt < 8; nt++) {                                        \
            int rb = (n0 + nt * 8 + g) * 20 + (j0) + tig;                       \
            bh[nt][0] = BsH[rb];  bh[nt][1] = BsH[rb + 4];                      \
            bl[nt][0] = BsL[rb];  bl[nt][1] = BsL[rb + 4];                      \
        }                                                                       \
        _Pragma("unroll")                                                       \
        for (int mt = 0; mt < 2; mt++)                                          \
            _Pragma("unroll")                                                   \
            for (int nt = 0; nt < 8; nt++) {                                    \
                MMA_BF16(acc[mt][nt], ah[mt], bh[nt]);                          \
                MMA_BF16(acc[mt][nt], ah[mt], bl[nt]);                          \
                MMA_BF16(acc[mt][nt], al[mt], bh[nt]);                          \
            }                                                                   \
    } while (0)

// ---------------- kernel 1: window-mean pool + RMS norm + exact GELU ----------
__global__ __launch_bounds__(256) void pool_norm_kernel(
    const float* __restrict__ x, const float* __restrict__ norm_w)
{
    int bid = blockIdx.x;            // 0..1023 = b*512 + p
    int b = bid >> 9, p = bid & 511;
    int tid = threadIdx.x;           // 256 threads, 6 channels each

    const float* xrow = x + ((size_t)b * S_ + (size_t)p * 16) * C_;

    float xp[6];
#pragma unroll
    for (int j = 0; j < 6; j++) xp[j] = 0.f;
    for (int r = 0; r < 16; r++) {
        const float* xr = xrow + (size_t)r * C_;
#pragma unroll
        for (int j = 0; j < 6; j++) xp[j] += xr[tid + j * 256];
    }
    float ssq = 0.f;
#pragma unroll
    for (int j = 0; j < 6; j++) { xp[j] *= (1.f / 16.f); ssq += xp[j] * xp[j]; }

    __shared__ float red[256];
    red[tid] = ssq;
    __syncthreads();
    for (int s = 128; s > 0; s >>= 1) {
        if (tid < s) red[tid] += red[tid + s];
        __syncthreads();
    }
    float scale = 1.f / sqrtf(red[0] * (1.f / (float)C_) + 1e-8f);

    float* xn_out = g_xn + (size_t)bid * C_;
    float* xg_out = g_xg + (size_t)bid * C_;
#pragma unroll
    for (int j = 0; j < 6; j++) {
        int ch = tid + j * 256;
        float v = xp[j] * scale * norm_w[ch];
        xn_out[ch] = v;
        xg_out[ch] = v * 0.5f * (1.f + erff(v * 0.70710678118654752f));
    }
}

// ---------------- kernel 2: central-mask features @ Wpos + bpos ---------------
__global__ __launch_bounds__(128) void pos_kernel(
    const float* __restrict__ Wpos, const float* __restrict__ bpos)
{
    int d   = blockIdx.x;            // 0..1023, rel = d - 512
    int tid = threadIdx.x;           // 128
    __shared__ float feat[32];

    int rel = d - P_;
    if (tid < 16) {
        double geo = exp((double)tid * (log(497.0) / 16.0));
        float center = (float)tid + (float)geo;
        float oh = (center > fabsf((float)rel)) ? 1.f : 0.f;
        float sg = (rel > 0) ? 1.f : ((rel < 0) ? -1.f : 0.f);
        feat[tid]      = oh;
        feat[tid + 16] = oh * sg;
    }
    __syncthreads();

    float f[32];
#pragma unroll
    for (int c = 0; c < 32; c++) f[c] = feat[c];

    for (int n = tid; n < HF; n += 128) {
        float acc = bpos[n];
#pragma unroll
        for (int c = 0; c < 32; c++) acc += f[c] * Wpos[c * HF + n];
        g_pos[(size_t)d * HF + n] = acc;
    }
}

// ---------------- kernel 3: MMA SGEMM NN (C[M,N] = A[M,K] @ B[K,N]) ------------
// 128x128 CTA tile, k-step 32, split bf16 hi/lo (3 MMAs). 8 warps 4(m)x2(n).
__global__ __launch_bounds__(256) void mma_nn_kernel(
    const float* __restrict__ A, const float* __restrict__ Bm,
    float* __restrict__ C, int M, int N, int K)
{
    __shared__ uint32_t AsH[128 * 20], AsL[128 * 20];
    __shared__ uint32_t BsH[128 * 20], BsL[128 * 20];

    int tid  = threadIdx.x;
    int warp = tid >> 5, lane = tid & 31;
    int g = lane >> 2, tig = lane & 3;
    int m0 = (warp >> 1) * 32, n0 = (warp & 1) * 64;
    int row0 = blockIdx.y * 128, col0 = blockIdx.x * 128;

    float acc[2][8][4];
#pragma unroll
    for (int i = 0; i < 2; i++)
#pragma unroll
        for (int j = 0; j < 8; j++)
#pragma unroll
            for (int l = 0; l < 4; l++) acc[i][j][l] = 0.f;

    for (int k0 = 0; k0 < K; k0 += 32) {
        // load A [M,K] rows -> AsH/AsL [m][k] (stride 20 u32 per row)
#pragma unroll
        for (int i = 0; i < 4; i++) {
            int t = tid + 256 * i;
            int r = t >> 3, c = t & 7;
            float4 v = *(const float4*)(A + (size_t)(row0 + r) * K + k0 + c * 4);
            uint32_t h0, l0, h1, l1;
            split2(v.x, v.y, h0, l0);
            split2(v.z, v.w, h1, l1);
            AsH[r * 20 + c * 2]     = h0;
            AsH[r * 20 + c * 2 + 1] = h1;
            AsL[r * 20 + c * 2]     = l0;
            AsL[r * 20 + c * 2 + 1] = l1;
        }
        // load B [K,N] -> Bs[n][k] (transposed scatter, bf16-granular stores)
        {
            __nv_bfloat16* bH = (__nv_bfloat16*)BsH;
            __nv_bfloat16* bL = (__nv_bfloat16*)BsL;
#pragma unroll
            for (int i = 0; i < 4; i++) {
                int t = tid + 256 * i;
                int r = t >> 5, c = t & 31;           // r = k index, c = n group
                float4 v = *(const float4*)(Bm + (size_t)(k0 + r) * N + col0 + c * 4);
                float vv[4] = {v.x, v.y, v.z, v.w};
#pragma unroll
                for (int j = 0; j < 4; j++) {
                    __nv_bfloat16 h = __float2bfloat16(vv[j]);
                    __nv_bfloat16 l = __float2bfloat16(vv[j] - __bfloat162float(h));
                    int n = c * 4 + j;
                    bH[n * 40 + r] = h;
                    bL[n * 40 + r] = l;
                }
            }
        }
        __syncthreads();
        FRAG_COMPUTE(AsH, AsL, BsH, BsL, 0);
        FRAG_COMPUTE(AsH, AsL, BsH, BsL, 8);
        __syncthreads();
    }

#pragma unroll
    for (int mt = 0; mt < 2; mt++)
#pragma unroll
        for (int nt = 0; nt < 8; nt++) {
            int r = row0 + m0 + mt * 16 + g;
            int cix = col0 + n0 + nt * 8 + tig * 2;
            *(float2*)(C + (size_t)r * N + cix) =
                make_float2(acc[mt][nt][0], acc[mt][nt][1]);
            *(float2*)(C + (size_t)(r + 8) * N + cix) =
                make_float2(acc[mt][nt][2], acc[mt][nt][3]);
        }
}

// ---------------- kernel 4: batched MMA SGEMM NT per (b,h) slice ---------------
// C[z][M][N] = alpha * (A+rowbias)[M,128] @ B[N,128]^T, lda=ldb=HF
__global__ __launch_bounds__(256) void mma_nt_kernel(
    const float* __restrict__ Abase, const float* __restrict__ Bbase,
    float* __restrict__ Cbase, const float* __restrict__ rowbias,
    int M, int N, int bInB, float alpha)
{
    int z = blockIdx.z;
    int b = z >> 5, h = z & 31;
    const float* A  = Abase + (size_t)b * P_ * HF + h * F_;
    const float* Bm = Bbase + (bInB ? (size_t)b * P_ * HF : 0) + h * F_;
    float* C = Cbase + (size_t)z * M * N;
    const float* bias = rowbias ? (rowbias + h * F_) : (const float*)0;

    __shared__ uint32_t AsH[128 * 20], AsL[128 * 20];
    __shared__ uint32_t BsH[128 * 20], BsL[128 * 20];

    int tid  = threadIdx.x;
    int warp = tid >> 5, lane = tid & 31;
    int g = lane >> 2, tig = lane & 3;
    int m0 = (warp >> 1) * 32, n0 = (warp & 1) * 64;
    int row0 = blockIdx.y * 128, col0 = blockIdx.x * 128;

    float acc[2][8][4];
#pragma unroll
    for (int i = 0; i < 2; i++)
#pragma unroll
        for (int j = 0; j < 8; j++)
#pragma unroll
            for (int l = 0; l < 4; l++) acc[i][j][l] = 0.f;

    for (int k0 = 0; k0 < 128; k0 += 32) {
        // load A rows (+bias) -> AsH/AsL
#pragma unroll
        for (int i = 0; i < 4; i++) {
            int t = tid + 256 * i;
            int r = t >> 3, c = t & 7;
            float4 v = *(const float4*)(A + (size_t)(row0 + r) * HF + k0 + c * 4);
            if (bias) {
                float4 bb = *(const float4*)(bias + k0 + c * 4);
                v.x += bb.x; v.y += bb.y; v.z += bb.z; v.w += bb.w;
            }
            uint32_t h0, l0, h1, l1;
            split2(v.x, v.y, h0, l0);
            split2(v.z, v.w, h1, l1);
            AsH[r * 20 + c * 2]     = h0;
            AsH[r * 20 + c * 2 + 1] = h1;
            AsL[r * 20 + c * 2]     = l0;
            AsL[r * 20 + c * 2 + 1] = l1;
        }
        // load B rows (n contiguous along k) -> BsH/BsL
#pragma unroll
        for (int i = 0; i < 4; i++) {
            int t = tid + 256 * i;
            int r = t >> 3, c = t & 7;
            float4 v = *(const float4*)(Bm + (size_t)(col0 + r) * HF + k0 + c * 4);
            uint32_t h0, l0, h1, l1;
            split2(v.x, v.y, h0, l0);
            split2(v.z, v.w, h1, l1);
            BsH[r * 20 + c * 2]     = h0;
            BsH[r * 20 + c * 2 + 1] = h1;
            BsL[r * 20 + c * 2]     = l0;
            BsL[r * 20 + c * 2 + 1] = l1;
        }
        __syncthreads();
        FRAG_COMPUTE(AsH, AsL, BsH, BsL, 0);
        FRAG_COMPUTE(AsH, AsL, BsH, BsL, 8);
        __syncthreads();
    }

#pragma unroll
    for (int mt = 0; mt < 2; mt++)
#pragma unroll
        for (int nt = 0; nt < 8; nt++) {
            int r = row0 + m0 + mt * 16 + g;
            int cix = col0 + n0 + nt * 8 + tig * 2;
            *(float2*)(C + (size_t)r * N + cix) =
                make_float2(acc[mt][nt][0] * alpha, acc[mt][nt][1] * alpha);
            *(float2*)(C + (size_t)(r + 8) * N + cix) =
                make_float2(acc[mt][nt][2] * alpha, acc[mt][nt][3] * alpha);
        }
}

// ---------------- kernel 5: fused gather + a@Wout epilogue --------------------
#define A_QSTRIDE 1057   // 32*33 + 1
#define A_KSTRIDE 33
#define SMEM_FINAL ((32 * A_QSTRIDE + 2 * 32 * 128) * 4)

__global__ __launch_bounds__(256) void final_kernel(
    const float* __restrict__ QK, const float* __restrict__ Qp,
    const float* __restrict__ Kp,
    const float* __restrict__ yq, const float* __restrict__ yk,
    const float* __restrict__ Wout, const float* __restrict__ bout,
    float* __restrict__ out)
{
    extern __shared__ float smem[];
    float* a_s  = smem;                      // 32*1057
    float* yq_s = smem + 32 * A_QSTRIDE;     // 32*128
    float* yk_s = yq_s + 32 * 128;           // 32*128

    int b  = blockIdx.z;
    int qt = blockIdx.y * 32;
    int kt = blockIdx.x * 32;
    int tid = threadIdx.x;

    for (int i = tid; i < 32 * 128; i += 256) {
        int q = i >> 7, f = i & 127;
        yq_s[i] = yq[((size_t)(b * P_) + qt + q) * F_ + f];
        yk_s[i] = yk[((size_t)(b * P_) + kt + q) * F_ + f];
    }

    // phase 1: a = QK + Qp (k innermost; contiguous in both sources)
    for (int i = tid; i < 32 * 32 * 32; i += 256) {
        int h = i >> 10, q = (i >> 5) & 31, k = i & 31;
        int gq = qt + q, gk = kt + k;
        size_t zb = (size_t)(b * 32 + h);
        float v = QK[(zb * P_ + gq) * P_ + gk]
                + Qp[(zb * P_ + gq) * P2 + (P_ + gk - gq)];
        a_s[q * A_QSTRIDE + k * A_KSTRIDE + h] = v;
    }
    __syncthreads();

    // phase 2: a += Kp (q innermost; Kp contiguous in q)
    for (int i = tid; i < 32 * 32 * 32; i += 256) {
        int h = i >> 10, k = (i >> 5) & 31, q = i & 31;
        int gq = qt + q, gk = kt + k;
        size_t zb = (size_t)(b * 32 + h);
        a_s[q * A_QSTRIDE + k * A_KSTRIDE + h] +=
            Kp[(zb * P_ + gk) * P2 + (P_ + gq - gk)];
    }
    __syncthreads();

    int lane = tid & 31, warp = tid >> 5;
    float w[32][4];
#pragma unroll
    for (int h = 0; h < 32; h++)
#pragma unroll
        for (int j = 0; j < 4; j++) w[h][j] = Wout[h * F_ + lane + j * 32];
    float bo[4];
#pragma unroll
    for (int j = 0; j < 4; j++) bo[j] = bout[lane + j * 32];

    for (int p = warp; p < 1024; p += 8) {
        int q = p >> 5, k = p & 31;
        const float* ap = a_s + q * A_QSTRIDE + k * A_KSTRIDE;
        float acc[4];
#pragma unroll
        for (int j = 0; j < 4; j++)
            acc[j] = bo[j] + yq_s[q * 128 + lane + j * 32]
                           + yk_s[k * 128 + lane + j * 32];
#pragma unroll
        for (int h = 0; h < 32; h++) {
            float ah = ap[h];
#pragma unroll
            for (int j = 0; j < 4; j++) acc[j] += ah * w[h][j];
        }
        float* orow = out + (((size_t)(b * P_) + qt + q) * P_ + kt + k) * F_ + lane;
#pragma unroll
        for (int j = 0; j < 4; j++) orow[j * 32] = acc[j];
    }
}

// ---------------- launch ------------------------------------------------------
extern "C" void kernel_launch(void* const* d_in, const int* in_sizes, int n_in,
                              void* d_out, int out_size)
{
    const float* x        = (const float*)d_in[0];
    const float* norm_w   = (const float*)d_in[1];
    const float* Wq       = (const float*)d_in[2];
    const float* Wk       = (const float*)d_in[3];
    const float* Wpos     = (const float*)d_in[4];
    const float* bpos     = (const float*)d_in[5];
    const float* q_r_bias = (const float*)d_in[6];
    const float* k_r_bias = (const float*)d_in[7];
    const float* Wyq      = (const float*)d_in[8];
    const float* Wyk      = (const float*)d_in[9];
    const float* Wout     = (const float*)d_in[10];
    const float* bout     = (const float*)d_in[11];
    float* out = (float*)d_out;

    float *p_xn, *p_xg, *p_q, *p_k, *p_pos, *p_yq, *p_yk, *p_QK, *p_Qp, *p_Kp;
    cudaGetSymbolAddress((void**)&p_xn,  g_xn);
    cudaGetSymbolAddress((void**)&p_xg,  g_xg);
    cudaGetSymbolAddress((void**)&p_q,   g_q);
    cudaGetSymbolAddress((void**)&p_k,   g_k);
    cudaGetSymbolAddress((void**)&p_pos, g_pos);
    cudaGetSymbolAddress((void**)&p_yq,  g_yq);
    cudaGetSymbolAddress((void**)&p_yk,  g_yk);
    cudaGetSymbolAddress((void**)&p_QK,  g_QK);
    cudaGetSymbolAddress((void**)&p_Qp,  g_Qp);
    cudaGetSymbolAddress((void**)&p_Kp,  g_Kp);

    pool_norm_kernel<<<1024, 256>>>(x, norm_w);
    pos_kernel<<<1024, 128>>>(Wpos, bpos);

    // projections (tensor core, split-bf16)
    mma_nn_kernel<<<dim3(HF / 128, 8), 256>>>(p_xn, Wq,  p_q,  1024, HF,  C_);
    mma_nn_kernel<<<dim3(HF / 128, 8), 256>>>(p_xn, Wk,  p_k,  1024, HF,  C_);
    mma_nn_kernel<<<dim3(1, 8),        256>>>(p_xg, Wyq, p_yq, 1024, 128, C_);
    mma_nn_kernel<<<dim3(1, 8),        256>>>(p_xg, Wyk, p_yk, 1024, 128, C_);

    // QK[b,h,q,k]; Qp[b,h,q,d] = 0.25*(q+qb)·pos; Kp[b,h,k,d] = 0.25*(k+kb)·pos
    mma_nt_kernel<<<dim3(4, 4, 64), 256>>>(p_q, p_k,   p_QK, (const float*)0, P_, P_, 1, 1.0f);
    mma_nt_kernel<<<dim3(8, 4, 64), 256>>>(p_q, p_pos, p_Qp, q_r_bias,        P_, P2, 0, 0.25f);
    mma_nt_kernel<<<dim3(8, 4, 64), 256>>>(p_k, p_pos, p_Kp, k_r_bias,        P_, P2, 0, 0.25f);

    cudaFuncSetAttribute(final_kernel,
                         cudaFuncAttributeMaxDynamicSharedMemorySize, SMEM_FINAL);
    final_kernel<<<dim3(16, 16, 2), 256, SMEM_FINAL>>>(
        p_QK, p_Qp, p_Kp, p_yq, p_yk, Wout, bout, out);
}

// round 3
// speedup vs baseline: 2.2428x; 1.9980x over previous
#include <cuda_runtime.h>
#include <cuda_bf16.h>
#include <math.h>
#include <stdint.h>

typedef __nv_bfloat16 bf16;

#define B_   2
#define S_   8192
#define C_   1536
#define P_   512
#define H_   32
#define F_   128
#define HF   4096
#define P2   1024
#define M_   1024     // B_*P_

// ---------------- scratch (device globals) ------------------------------------
__device__ __align__(16) bf16 g_xnh[M_ * C_], g_xnl[M_ * C_];
__device__ __align__(16) bf16 g_xgh[M_ * C_], g_xgl[M_ * C_];
__device__ __align__(16) bf16 g_wqth[HF * C_], g_wqtl[HF * C_];
__device__ __align__(16) bf16 g_wkth[HF * C_], g_wktl[HF * C_];
__device__ __align__(16) bf16 g_wyqh[F_ * C_], g_wyql[F_ * C_];
__device__ __align__(16) bf16 g_wykh[F_ * C_], g_wykl[F_ * C_];
__device__ __align__(16) bf16 g_posh[P2 * HF], g_posl[P2 * HF];
__device__ __align__(16) bf16 g_qh [M_ * HF], g_ql [M_ * HF];
__device__ __align__(16) bf16 g_qbh[M_ * HF], g_qbl[M_ * HF];
__device__ __align__(16) bf16 g_kh [M_ * HF], g_kl [M_ * HF];
__device__ __align__(16) bf16 g_kbh[M_ * HF], g_kbl[M_ * HF];
__device__ float g_ypart[8 * M_ * F_];                     // [which*4+ksplit][1024][128]
__device__ float g_QK [(size_t)B_ * H_ * P_ * P_];
__device__ float g_Qp [(size_t)B_ * H_ * P_ * P2];
__device__ float g_Kp [(size_t)B_ * H_ * P_ * P2];

// ---------------- helpers ------------------------------------------------------
__device__ __forceinline__ void split2(float x, float y, uint32_t& hw, uint32_t& lw)
{
    __nv_bfloat16 hx = __float2bfloat16(x);
    __nv_bfloat16 hy = __float2bfloat16(y);
    __nv_bfloat16 lx = __float2bfloat16(x - __bfloat162float(hx));
    __nv_bfloat16 ly = __float2bfloat16(y - __bfloat162float(hy));
    __nv_bfloat162 hp = __halves2bfloat162(hx, hy);
    __nv_bfloat162 lp = __halves2bfloat162(lx, ly);
    hw = *reinterpret_cast<uint32_t*>(&hp);
    lw = *reinterpret_cast<uint32_t*>(&lp);
}

__device__ __forceinline__ void cp16(uint32_t* smem_ptr, const bf16* gptr)
{
    uint32_t s = (uint32_t)__cvta_generic_to_shared(smem_ptr);
    asm volatile("cp.async.cg.shared.global [%0], [%1], 16;\n" :: "r"(s), "l"(gptr));
}

#define MMA_BF16(c, a, b)                                                       \
    asm volatile(                                                               \
        "mma.sync.aligned.m16n8k16.row.col.f32.bf16.bf16.f32 "                  \
        "{%0,%1,%2,%3}, {%4,%5,%6,%7}, {%8,%9}, {%0,%1,%2,%3};\n"               \
        : "+f"((c)[0]), "+f"((c)[1]), "+f"((c)[2]), "+f"((c)[3])                \
        : "r"((a)[0]), "r"((a)[1]), "r"((a)[2]), "r"((a)[3]),                   \
          "r"((b)[0]), "r"((b)[1]))

#define FRAG_COMPUTE(AsH, AsL, BsH, BsL, j0)                                    \
    do {                                                                        \
        uint32_t ah[2][4], al[2][4], bh[8][2], bl[8][2];                        \
        _Pragma("unroll")                                                       \
        for (int mt = 0; mt < 2; mt++) {                                        \
            int rb = (m0 + mt * 16 + g) * 20 + (j0) + tig;                      \
            ah[mt][0] = (AsH)[rb];       ah[mt][1] = (AsH)[rb + 160];           \
            ah[mt][2] = (AsH)[rb + 4];   ah[mt][3] = (AsH)[rb + 164];           \
            al[mt][0] = (AsL)[rb];       al[mt][1] = (AsL)[rb + 160];           \
            al[mt][2] = (AsL)[rb + 4];   al[mt][3] = (AsL)[rb + 164];           \
        }                                                                       \
        _Pragma("unroll")                                                       \
        for (int nt = 0; nt < 8; nt++) {                                        \
            int rb = (n0 + nt * 8 + g) * 20 + (j0) + tig;                       \
            bh[nt][0] = (BsH)[rb];  bh[nt][1] = (BsH)[rb + 4];                  \
            bl[nt][0] = (BsL)[rb];  bl[nt][1] = (BsL)[rb + 4];                  \
        }                                                                       \
        _Pragma("unroll")                                                       \
        for (int mt = 0; mt < 2; mt++)                                          \
            _Pragma("unroll")                                                   \
            for (int nt = 0; nt < 8; nt++) {                                    \
                MMA_BF16(acc[mt][nt], ah[mt], bh[nt]);                          \
                MMA_BF16(acc[mt][nt], ah[mt], bl[nt]);                          \
                MMA_BF16(acc[mt][nt], al[mt], bh[nt]);                          \
            }                                                                   \
    } while (0)

// 2-stage cp.async pipelined mainloop over K window.
// Expects: sm (dyn smem), tid, rowA0, col0, m0, n0, g, tig, acc declared.
#define LOAD_STAGE(s, kpos, Ah, Al, Bh, Bl, lda, ldb)                           \
    {                                                                           \
        uint32_t* sb = sm + (s) * 10240;                                        \
        _Pragma("unroll")                                                       \
        for (int ci = 0; ci < 2; ci++) {                                        \
            int qq = tid + ci * 256;                                            \
            int rw = qq >> 2, cc = qq & 3;                                      \
            uint32_t so = rw * 20 + cc * 4;                                     \
            size_t ga = (size_t)(rowA0 + rw) * (lda) + (kpos) + cc * 8;         \
            size_t gb = (size_t)(col0 + rw) * (ldb) + (kpos) + cc * 8;          \
            cp16(sb + so,        (Ah) + ga);                                    \
            cp16(sb + 2560 + so, (Al) + ga);                                    \
            cp16(sb + 5120 + so, (Bh) + gb);                                    \
            cp16(sb + 7680 + so, (Bl) + gb);                                    \
        }                                                                       \
    }

#define GEMM_MAIN(Ah, Al, Bh, Bl, lda, ldb, kb, nk)                             \
    {                                                                           \
        LOAD_STAGE(0, (kb), Ah, Al, Bh, Bl, lda, ldb);                          \
        asm volatile("cp.async.commit_group;\n");                               \
        for (int it = 0; it < (nk); it++) {                                     \
            if (it + 1 < (nk)) {                                                \
                LOAD_STAGE((it + 1) & 1, (kb) + (it + 1) * 32,                  \
                           Ah, Al, Bh, Bl, lda, ldb);                           \
                asm volatile("cp.async.commit_group;\n");                       \
                asm volatile("cp.async.wait_group 1;\n");                       \
            } else {                                                            \
                asm volatile("cp.async.wait_group 0;\n");                       \
            }                                                                   \
            __syncthreads();                                                    \
            uint32_t* st = sm + (it & 1) * 10240;                               \
            FRAG_COMPUTE(st, st + 2560, st + 5120, st + 7680, 0);               \
            FRAG_COMPUTE(st, st + 2560, st + 5120, st + 7680, 8);               \
            __syncthreads();                                                    \
        }                                                                       \
    }

#define GEMM_PREAMBLE                                                           \
    extern __shared__ uint32_t sm[];                                            \
    int tid = threadIdx.x;                                                      \
    int warp = tid >> 5, lane = tid & 31;                                       \
    int g = lane >> 2, tig = lane & 3;                                          \
    int m0 = (warp >> 1) * 32, n0 = (warp & 1) * 64;                            \
    float acc[2][8][4];                                                         \
    _Pragma("unroll")                                                           \
    for (int i = 0; i < 2; i++)                                                 \
        _Pragma("unroll")                                                       \
        for (int j = 0; j < 8; j++)                                             \
            _Pragma("unroll")                                                   \
            for (int l = 0; l < 4; l++) acc[i][j][l] = 0.f;

#define EPI_F32(Cp, ldc, alpha)                                                 \
    _Pragma("unroll")                                                           \
    for (int mt = 0; mt < 2; mt++)                                              \
        _Pragma("unroll")                                                       \
        for (int nt = 0; nt < 8; nt++) {                                        \
            int r = rowA0 + m0 + mt * 16 + g;                                   \
            int cix = col0 + n0 + nt * 8 + tig * 2;                             \
            *(float2*)((Cp) + (size_t)r * (ldc) + cix) =                        \
                make_float2(acc[mt][nt][0] * (alpha), acc[mt][nt][1] * (alpha));\
            *(float2*)((Cp) + (size_t)(r + 8) * (ldc) + cix) =                  \
                make_float2(acc[mt][nt][2] * (alpha), acc[mt][nt][3] * (alpha));\
        }

#define GEMM_SMEM 81920

// ---------------- kernel: pool + RMS norm + GELU, split-bf16 out --------------
__global__ __launch_bounds__(256) void pool_norm_kernel(
    const float* __restrict__ x, const float* __restrict__ norm_w)
{
    int bid = blockIdx.x;
    int b = bid >> 9, p = bid & 511;
    int tid = threadIdx.x;

    const float* xrow = x + ((size_t)b * S_ + (size_t)p * 16) * C_;
    float xp[6];
#pragma unroll
    for (int j = 0; j < 6; j++) xp[j] = 0.f;
    for (int r = 0; r < 16; r++) {
        const float* xr = xrow + (size_t)r * C_;
#pragma unroll
        for (int j = 0; j < 6; j++) xp[j] += xr[tid + j * 256];
    }
    float ssq = 0.f;
#pragma unroll
    for (int j = 0; j < 6; j++) { xp[j] *= (1.f / 16.f); ssq += xp[j] * xp[j]; }

    __shared__ float red[256];
    red[tid] = ssq;
    __syncthreads();
    for (int s = 128; s > 0; s >>= 1) {
        if (tid < s) red[tid] += red[tid + s];
        __syncthreads();
    }
    float scale = 1.f / sqrtf(red[0] * (1.f / (float)C_) + 1e-8f);

    size_t base = (size_t)bid * C_;
#pragma unroll
    for (int j = 0; j < 6; j++) {
        int ch = tid + j * 256;
        float v = xp[j] * scale * norm_w[ch];
        float gv = v * 0.5f * (1.f + erff(v * 0.70710678118654752f));
        bf16 h = __float2bfloat16(v);
        g_xnh[base + ch] = h;
        g_xnl[base + ch] = __float2bfloat16(v - __bfloat162float(h));
        bf16 gh = __float2bfloat16(gv);
        g_xgh[base + ch] = gh;
        g_xgl[base + ch] = __float2bfloat16(gv - __bfloat162float(gh));
    }
}

// ---------------- kernel: pos features @ Wpos + bpos, split-bf16 out ----------
__global__ __launch_bounds__(128) void pos_kernel(
    const float* __restrict__ Wpos, const float* __restrict__ bpos)
{
    int d   = blockIdx.x;
    int tid = threadIdx.x;
    __shared__ float feat[32];

    int rel = d - P_;
    if (tid < 16) {
        double geo = exp((double)tid * (log(497.0) / 16.0));
        float center = (float)tid + (float)geo;
        float oh = (center > fabsf((float)rel)) ? 1.f : 0.f;
        float sg = (rel > 0) ? 1.f : ((rel < 0) ? -1.f : 0.f);
        feat[tid]      = oh;
        feat[tid + 16] = oh * sg;
    }
    __syncthreads();

    float f[32];
#pragma unroll
    for (int c = 0; c < 32; c++) f[c] = feat[c];

    for (int n = tid; n < HF; n += 128) {
        float acc = bpos[n];
#pragma unroll
        for (int c = 0; c < 32; c++) acc += f[c] * Wpos[c * HF + n];
        bf16 h = __float2bfloat16(acc);
        g_posh[(size_t)d * HF + n] = h;
        g_posl[(size_t)d * HF + n] = __float2bfloat16(acc - __bfloat162float(h));
    }
}

// ---------------- kernel: weight transpose-convert W[K,N] -> T[N,K] split ------
__global__ __launch_bounds__(256) void wconv_kernel(
    const float* __restrict__ W, bf16* __restrict__ Th, bf16* __restrict__ Tl,
    int K, int N)
{
    __shared__ float t[32][33];
    int nt0 = blockIdx.x * 32, kt0 = blockIdx.y * 32;
    int tx = threadIdx.x & 31, ty = threadIdx.x >> 5;
#pragma unroll
    for (int i = 0; i < 4; i++)
        t[ty + i * 8][tx] = W[(size_t)(kt0 + ty + i * 8) * N + nt0 + tx];
    __syncthreads();
#pragma unroll
    for (int i = 0; i < 4; i++) {
        int n = nt0 + ty + i * 8, k = kt0 + tx;
        float v = t[tx][ty + i * 8];
        bf16 h = __float2bfloat16(v);
        Th[(size_t)n * K + k] = h;
        Tl[(size_t)n * K + k] = __float2bfloat16(v - __bfloat162float(h));
    }
}

// ---------------- kernel: projection GEMM (q/k), split-bf16 epilogue ----------
// C[1024,4096] = A[1024,1536] @ B[4096,1536]^T; writes raw split + biased split
__global__ __launch_bounds__(256, 2) void proj_gemm(
    const bf16* __restrict__ Ah, const bf16* __restrict__ Al,
    const bf16* __restrict__ Bh, const bf16* __restrict__ Bl,
    const float* __restrict__ bias,
    bf16* __restrict__ Oh, bf16* __restrict__ Ol,
    bf16* __restrict__ OBh, bf16* __restrict__ OBl)
{
    GEMM_PREAMBLE
    int rowA0 = blockIdx.y * 128, col0 = blockIdx.x * 128;
    GEMM_MAIN(Ah, Al, Bh, Bl, C_, C_, 0, C_ / 32);

    uint32_t* oh  = (uint32_t*)Oh;
    uint32_t* ol  = (uint32_t*)Ol;
    uint32_t* obh = (uint32_t*)OBh;
    uint32_t* obl = (uint32_t*)OBl;
#pragma unroll
    for (int mt = 0; mt < 2; mt++)
#pragma unroll
        for (int nt = 0; nt < 8; nt++) {
            int r = rowA0 + m0 + mt * 16 + g;
            int n = col0 + n0 + nt * 8 + tig * 2;
            float2 bb = *(const float2*)(bias + n);
            uint32_t hw, lw;
            size_t ix0 = ((size_t)r * HF + n) >> 1;
            size_t ix1 = ((size_t)(r + 8) * HF + n) >> 1;
            split2(acc[mt][nt][0], acc[mt][nt][1], hw, lw);
            oh[ix0] = hw; ol[ix0] = lw;
            split2(acc[mt][nt][0] + bb.x, acc[mt][nt][1] + bb.y, hw, lw);
            obh[ix0] = hw; obl[ix0] = lw;
            split2(acc[mt][nt][2], acc[mt][nt][3], hw, lw);
            oh[ix1] = hw; ol[ix1] = lw;
            split2(acc[mt][nt][2] + bb.x, acc[mt][nt][3] + bb.y, hw, lw);
            obh[ix1] = hw; obl[ix1] = lw;
        }
}

// ---------------- kernel: yq/yk GEMM, split-K x4, both outputs ----------------
__global__ __launch_bounds__(256, 2) void y_gemm(
    const bf16* __restrict__ Ah, const bf16* __restrict__ Al,
    const bf16* __restrict__ B0h, const bf16* __restrict__ B0l,
    const bf16* __restrict__ B1h, const bf16* __restrict__ B1l,
    float* __restrict__ ypart)
{
    GEMM_PREAMBLE
    int z = blockIdx.z;
    const bf16* Bh = (z >= 4) ? B1h : B0h;
    const bf16* Bl = (z >= 4) ? B1l : B0l;
    int kb = (z & 3) * 384;
    int rowA0 = blockIdx.y * 128, col0 = 0;
    GEMM_MAIN(Ah, Al, Bh, Bl, C_, C_, kb, 12);
    float* C = ypart + (size_t)z * M_ * F_;
    EPI_F32(C, F_, 1.0f)
}

// ---------------- kernel: batched relative GEMM (QK / Qp / Kp) ----------------
__global__ __launch_bounds__(256, 2) void rel_gemm(
    const bf16* __restrict__ Ahb, const bf16* __restrict__ Alb,
    const bf16* __restrict__ Bhb, const bf16* __restrict__ Blb,
    float* __restrict__ Cbase, int N, int bInB, float alpha)
{
    GEMM_PREAMBLE
    int z = blockIdx.z, b = z >> 5, h = z & 31;
    const bf16* Ah = Ahb + (size_t)b * P_ * HF + h * F_;
    const bf16* Al = Alb + (size_t)b * P_ * HF + h * F_;
    const bf16* Bh = Bhb + (bInB ? (size_t)b * P_ * HF : 0) + h * F_;
    const bf16* Bl = Blb + (bInB ? (size_t)b * P_ * HF : 0) + h * F_;
    float* C = Cbase + (size_t)z * P_ * N;
    int rowA0 = blockIdx.y * 128, col0 = blockIdx.x * 128;
    GEMM_MAIN(Ah, Al, Bh, Bl, HF, HF, 0, 4);
    EPI_F32(C, N, alpha)
}

// ---------------- kernel: fused gather + a@Wout epilogue ----------------------
#define A_QSTRIDE 1057
#define A_KSTRIDE 33
#define SMEM_FINAL ((32 * A_QSTRIDE + 2 * 32 * 128) * 4)
#define M128 (M_ * F_)

__global__ __launch_bounds__(256) void final_kernel(
    const float* __restrict__ QK, const float* __restrict__ Qp,
    const float* __restrict__ Kp, const float* __restrict__ ypart,
    const float* __restrict__ Wout, const float* __restrict__ bout,
    float* __restrict__ out)
{
    extern __shared__ float smem[];
    float* a_s  = smem;
    float* yq_s = smem + 32 * A_QSTRIDE;
    float* yk_s = yq_s + 32 * 128;

    int b  = blockIdx.z;
    int qt = blockIdx.y * 32;
    int kt = blockIdx.x * 32;
    int tid = threadIdx.x;

    for (int i = tid; i < 32 * 128; i += 256) {
        int q = i >> 7, f = i & 127;
        size_t rq = ((size_t)(b * P_ + qt + q)) * F_ + f;
        size_t rk = ((size_t)(b * P_ + kt + q)) * F_ + f;
        float vq = 0.f, vk = 0.f;
#pragma unroll
        for (int s = 0; s < 4; s++) {
            vq += ypart[(size_t)s * M128 + rq];
            vk += ypart[(size_t)(4 + s) * M128 + rk];
        }
        yq_s[i] = vq;
        yk_s[i] = vk;
    }

    // phase 1: a = QK + Qp (k innermost)
    for (int i = tid; i < 32 * 32 * 32; i += 256) {
        int h = i >> 10, q = (i >> 5) & 31, k = i & 31;
        int gq = qt + q, gk = kt + k;
        size_t zb = (size_t)(b * 32 + h);
        float v = QK[(zb * P_ + gq) * P_ + gk]
                + Qp[(zb * P_ + gq) * P2 + (P_ + gk - gq)];
        a_s[q * A_QSTRIDE + k * A_KSTRIDE + h] = v;
    }
    __syncthreads();

    // phase 2: a += Kp (q innermost)
    for (int i = tid; i < 32 * 32 * 32; i += 256) {
        int h = i >> 10, k = (i >> 5) & 31, q = i & 31;
        int gq = qt + q, gk = kt + k;
        size_t zb = (size_t)(b * 32 + h);
        a_s[q * A_QSTRIDE + k * A_KSTRIDE + h] +=
            Kp[(zb * P_ + gk) * P2 + (P_ + gq - gk)];
    }
    __syncthreads();

    int lane = tid & 31, warp = tid >> 5;
    float w[32][4];
#pragma unroll
    for (int h = 0; h < 32; h++)
#pragma unroll
        for (int j = 0; j < 4; j++) w[h][j] = Wout[h * F_ + lane + j * 32];
    float bo[4];
#pragma unroll
    for (int j = 0; j < 4; j++) bo[j] = bout[lane + j * 32];

    for (int p = warp; p < 1024; p += 8) {
        int q = p >> 5, k = p & 31;
        const float* ap = a_s + q * A_QSTRIDE + k * A_KSTRIDE;
        float acc[4];
#pragma unroll
        for (int j = 0; j < 4; j++)
            acc[j] = bo[j] + yq_s[q * 128 + lane + j * 32]
                           + yk_s[k * 128 + lane + j * 32];
#pragma unroll
        for (int h = 0; h < 32; h++) {
            float ah = ap[h];
#pragma unroll
            for (int j = 0; j < 4; j++) acc[j] += ah * w[h][j];
        }
        float* orow = out + (((size_t)(b * P_) + qt + q) * P_ + kt + k) * F_ + lane;
#pragma unroll
        for (int j = 0; j < 4; j++) orow[j * 32] = acc[j];
    }
}

// ---------------- launch ------------------------------------------------------
extern "C" void kernel_launch(void* const* d_in, const int* in_sizes, int n_in,
                              void* d_out, int out_size)
{
    const float* x        = (const float*)d_in[0];
    const float* norm_w   = (const float*)d_in[1];
    const float* Wq       = (const float*)d_in[2];
    const float* Wk       = (const float*)d_in[3];
    const float* Wpos     = (const float*)d_in[4];
    const float* bpos     = (const float*)d_in[5];
    const float* q_r_bias = (const float*)d_in[6];
    const float* k_r_bias = (const float*)d_in[7];
    const float* Wyq      = (const float*)d_in[8];
    const float* Wyk      = (const float*)d_in[9];
    const float* Wout     = (const float*)d_in[10];
    const float* bout     = (const float*)d_in[11];
    float* out = (float*)d_out;

    bf16 *p_xnh, *p_xnl, *p_xgh, *p_xgl;
    bf16 *p_wqth, *p_wqtl, *p_wkth, *p_wktl, *p_wyqh, *p_wyql, *p_wykh, *p_wykl;
    bf16 *p_posh, *p_posl;
    bf16 *p_qh, *p_ql, *p_qbh, *p_qbl, *p_kh, *p_kl, *p_kbh, *p_kbl;
    float *p_ypart, *p_QK, *p_Qp, *p_Kp;
    cudaGetSymbolAddress((void**)&p_xnh,  g_xnh);
    cudaGetSymbolAddress((void**)&p_xnl,  g_xnl);
    cudaGetSymbolAddress((void**)&p_xgh,  g_xgh);
    cudaGetSymbolAddress((void**)&p_xgl,  g_xgl);
    cudaGetSymbolAddress((void**)&p_wqth, g_wqth);
    cudaGetSymbolAddress((void**)&p_wqtl, g_wqtl);
    cudaGetSymbolAddress((void**)&p_wkth, g_wkth);
    cudaGetSymbolAddress((void**)&p_wktl, g_wktl);
    cudaGetSymbolAddress((void**)&p_wyqh, g_wyqh);
    cudaGetSymbolAddress((void**)&p_wyql, g_wyql);
    cudaGetSymbolAddress((void**)&p_wykh, g_wykh);
    cudaGetSymbolAddress((void**)&p_wykl, g_wykl);
    cudaGetSymbolAddress((void**)&p_posh, g_posh);
    cudaGetSymbolAddress((void**)&p_posl, g_posl);
    cudaGetSymbolAddress((void**)&p_qh,   g_qh);
    cudaGetSymbolAddress((void**)&p_ql,   g_ql);
    cudaGetSymbolAddress((void**)&p_qbh,  g_qbh);
    cudaGetSymbolAddress((void**)&p_qbl,  g_qbl);
    cudaGetSymbolAddress((void**)&p_kh,   g_kh);
    cudaGetSymbolAddress((void**)&p_kl,   g_kl);
    cudaGetSymbolAddress((void**)&p_kbh,  g_kbh);
    cudaGetSymbolAddress((void**)&p_kbl,  g_kbl);
    cudaGetSymbolAddress((void**)&p_ypart, g_ypart);
    cudaGetSymbolAddress((void**)&p_QK,   g_QK);
    cudaGetSymbolAddress((void**)&p_Qp,   g_Qp);
    cudaGetSymbolAddress((void**)&p_Kp,   g_Kp);

    cudaFuncSetAttribute(proj_gemm, cudaFuncAttributeMaxDynamicSharedMemorySize, GEMM_SMEM);
    cudaFuncSetAttribute(y_gemm,    cudaFuncAttributeMaxDynamicSharedMemorySize, GEMM_SMEM);
    cudaFuncSetAttribute(rel_gemm,  cudaFuncAttributeMaxDynamicSharedMemorySize, GEMM_SMEM);
    cudaFuncSetAttribute(final_kernel, cudaFuncAttributeMaxDynamicSharedMemorySize, SMEM_FINAL);

    // prep: convert operands once
    pool_norm_kernel<<<1024, 256>>>(x, norm_w);
    pos_kernel<<<1024, 128>>>(Wpos, bpos);
    wconv_kernel<<<dim3(128, 48), 256>>>(Wq,  p_wqth, p_wqtl, C_, HF);
    wconv_kernel<<<dim3(128, 48), 256>>>(Wk,  p_wkth, p_wktl, C_, HF);
    wconv_kernel<<<dim3(4, 48),   256>>>(Wyq, p_wyqh, p_wyql, C_, F_);
    wconv_kernel<<<dim3(4, 48),   256>>>(Wyk, p_wykh, p_wykl, C_, F_);

    // projections
    proj_gemm<<<dim3(32, 8), 256, GEMM_SMEM>>>(
        p_xnh, p_xnl, p_wqth, p_wqtl, q_r_bias, p_qh, p_ql, p_qbh, p_qbl);
    proj_gemm<<<dim3(32, 8), 256, GEMM_SMEM>>>(
        p_xnh, p_xnl, p_wkth, p_wktl, k_r_bias, p_kh, p_kl, p_kbh, p_kbl);
    y_gemm<<<dim3(1, 8, 8), 256, GEMM_SMEM>>>(
        p_xgh, p_xgl, p_wyqh, p_wyql, p_wykh, p_wykl, p_ypart);

    // relative GEMMs
    rel_gemm<<<dim3(4, 4, 64), 256, GEMM_SMEM>>>(
        p_qh, p_ql, p_kh, p_kl, p_QK, P_, 1, 1.0f);
    rel_gemm<<<dim3(8, 4, 64), 256, GEMM_SMEM>>>(
        p_qbh, p_qbl, p_posh, p_posl, p_Qp, P2, 0, 0.25f);
    rel_gemm<<<dim3(8, 4, 64), 256, GEMM_SMEM>>>(
        p_kbh, p_kbl, p_posh, p_posl, p_Kp, P2, 0, 0.25f);

    final_kernel<<<dim3(16, 16, 2), 256, SMEM_FINAL>>>(
        p_QK, p_Qp, p_Kp, p_ypart, Wout, bout, out);
}

// round 4
// speedup vs baseline: 2.3421x; 1.0443x over previous
#include <cuda_runtime.h>
#include <cuda_bf16.h>
#include <math.h>
#include <stdint.h>

typedef __nv_bfloat16 bf16;

#define B_   2
#define S_   8192
#define C_   1536
#define P_   512
#define H_   32
#define F_   128
#define HF   4096
#define P2   1024
#define M_   1024     // B_*P_

// ---------------- scratch (device globals) ------------------------------------
__device__ __align__(16) bf16 g_xnh[M_ * C_], g_xnl[M_ * C_];
__device__ __align__(16) bf16 g_xgh[M_ * C_], g_xgl[M_ * C_];
__device__ __align__(16) bf16 g_wqth[HF * C_], g_wqtl[HF * C_];
__device__ __align__(16) bf16 g_wkth[HF * C_], g_wktl[HF * C_];
__device__ __align__(16) bf16 g_wyqh[F_ * C_], g_wyql[F_ * C_];
__device__ __align__(16) bf16 g_wykh[F_ * C_], g_wykl[F_ * C_];
__device__ __align__(16) bf16 g_posh[P2 * HF], g_posl[P2 * HF];
__device__ __align__(16) bf16 g_qh [M_ * HF], g_ql [M_ * HF];
__device__ __align__(16) bf16 g_kh [M_ * HF], g_kl [M_ * HF];
__device__ float g_bias [2 * H_ * P2];                     // [sel][h][d], pre-scaled 0.25
__device__ float g_ypart[8 * M_ * F_];
__device__ float g_QK [(size_t)B_ * H_ * P_ * P_];
__device__ float g_Qp [(size_t)B_ * H_ * P_ * P2];
__device__ float g_Kp [(size_t)B_ * H_ * P_ * P2];

// ---------------- helpers ------------------------------------------------------
__device__ __forceinline__ void split2(float x, float y, uint32_t& hw, uint32_t& lw)
{
    __nv_bfloat16 hx = __float2bfloat16(x);
    __nv_bfloat16 hy = __float2bfloat16(y);
    __nv_bfloat16 lx = __float2bfloat16(x - __bfloat162float(hx));
    __nv_bfloat16 ly = __float2bfloat16(y - __bfloat162float(hy));
    __nv_bfloat162 hp = __halves2bfloat162(hx, hy);
    __nv_bfloat162 lp = __halves2bfloat162(lx, ly);
    hw = *reinterpret_cast<uint32_t*>(&hp);
    lw = *reinterpret_cast<uint32_t*>(&lp);
}

__device__ __forceinline__ void cp16(uint32_t* smem_ptr, const bf16* gptr)
{
    uint32_t s = (uint32_t)__cvta_generic_to_shared(smem_ptr);
    asm volatile("cp.async.cg.shared.global [%0], [%1], 16;\n" :: "r"(s), "l"(gptr));
}

#define MMA_BF16(c, a, b)                                                       \
    asm volatile(                                                               \
        "mma.sync.aligned.m16n8k16.row.col.f32.bf16.bf16.f32 "                  \
        "{%0,%1,%2,%3}, {%4,%5,%6,%7}, {%8,%9}, {%0,%1,%2,%3};\n"               \
        : "+f"((c)[0]), "+f"((c)[1]), "+f"((c)[2]), "+f"((c)[3])                \
        : "r"((a)[0]), "r"((a)[1]), "r"((a)[2]), "r"((a)[3]),                   \
          "r"((b)[0]), "r"((b)[1]))

#define LDSM4(d0, d1, d2, d3, a)                                                \
    asm volatile(                                                               \
        "ldmatrix.sync.aligned.m8n8.x4.shared.b16 {%0,%1,%2,%3}, [%4];\n"       \
        : "=r"(d0), "=r"(d1), "=r"(d2), "=r"(d3) : "r"(a))

// one k16 sub-step: ldmatrix fragments + 48 MMAs. sst = stage base (shared addr, bytes)
#define FRAG_LDSM(sst, j0)                                                      \
    do {                                                                        \
        uint32_t ah[2][4], al[2][4], bh[8][2], bl[8][2];                        \
        _Pragma("unroll")                                                       \
        for (int mt = 0; mt < 2; mt++) {                                        \
            uint32_t aa = (sst) + aoff + mt * 1280u + (j0) * 4u;                \
            LDSM4(ah[mt][0], ah[mt][1], ah[mt][2], ah[mt][3], aa);              \
            LDSM4(al[mt][0], al[mt][1], al[mt][2], al[mt][3], aa + 10240u);     \
        }                                                                       \
        _Pragma("unroll")                                                       \
        for (int tp = 0; tp < 4; tp++) {                                        \
            uint32_t ba = (sst) + boff + tp * 1280u + (j0) * 4u + 20480u;       \
            LDSM4(bh[2*tp][0], bh[2*tp+1][0], bh[2*tp][1], bh[2*tp+1][1], ba);  \
            LDSM4(bl[2*tp][0], bl[2*tp+1][0], bl[2*tp][1], bl[2*tp+1][1],       \
                  ba + 10240u);                                                 \
        }                                                                       \
        _Pragma("unroll")                                                       \
        for (int mt = 0; mt < 2; mt++)                                          \
            _Pragma("unroll")                                                   \
            for (int nt = 0; nt < 8; nt++) {                                    \
                MMA_BF16(acc[mt][nt], ah[mt], bh[nt]);                          \
                MMA_BF16(acc[mt][nt], ah[mt], bl[nt]);                          \
                MMA_BF16(acc[mt][nt], al[mt], bh[nt]);                          \
            }                                                                   \
    } while (0)

#define LOAD_STAGE(s, kpos, Ah, Al, Bh, Bl, lda, ldb)                           \
    {                                                                           \
        uint32_t* sb = sm + (s) * 10240;                                        \
        _Pragma("unroll")                                                       \
        for (int ci = 0; ci < 2; ci++) {                                        \
            int qq = tid + ci * 256;                                            \
            int rw = qq >> 2, cc = qq & 3;                                      \
            uint32_t so = rw * 20 + cc * 4;                                     \
            size_t ga = (size_t)(rowA0 + rw) * (lda) + (kpos) + cc * 8;         \
            size_t gb = (size_t)(col0 + rw) * (ldb) + (kpos) + cc * 8;          \
            cp16(sb + so,        (Ah) + ga);                                    \
            cp16(sb + 2560 + so, (Al) + ga);                                    \
            cp16(sb + 5120 + so, (Bh) + gb);                                    \
            cp16(sb + 7680 + so, (Bl) + gb);                                    \
        }                                                                       \
    }

// 2-stage pipeline, ONE barrier per iter, prefetch between k16 halves
#define GEMM_MAIN(Ah, Al, Bh, Bl, lda, ldb, kb, nk)                             \
    {                                                                           \
        LOAD_STAGE(0, (kb), Ah, Al, Bh, Bl, lda, ldb);                          \
        asm volatile("cp.async.commit_group;\n");                               \
        for (int it = 0; it < (nk); it++) {                                     \
            asm volatile("cp.async.wait_group 0;\n");                           \
            __syncthreads();                                                    \
            uint32_t sst = smb + (uint32_t)((it & 1) * 40960);                  \
            FRAG_LDSM(sst, 0);                                                  \
            if (it + 1 < (nk)) {                                                \
                LOAD_STAGE((it + 1) & 1, (kb) + (it + 1) * 32,                  \
                           Ah, Al, Bh, Bl, lda, ldb);                           \
                asm volatile("cp.async.commit_group;\n");                       \
            }                                                                   \
            FRAG_LDSM(sst, 8);                                                  \
        }                                                                       \
    }

#define GEMM_PREAMBLE                                                           \
    extern __shared__ uint32_t sm[];                                            \
    uint32_t smb = (uint32_t)__cvta_generic_to_shared(sm);                      \
    int tid = threadIdx.x;                                                      \
    int warp = tid >> 5, lane = tid & 31;                                       \
    int g = lane >> 2, tig = lane & 3;                                          \
    int lr = lane & 15, lh = lane >> 4;                                         \
    int m0 = (warp >> 1) * 32, n0 = (warp & 1) * 64;                            \
    uint32_t aoff = ((m0 + lr) * 20 + lh * 4) * 4;                              \
    uint32_t boff = ((n0 + lr) * 20 + lh * 4) * 4;                              \
    float acc[2][8][4];                                                         \
    _Pragma("unroll")                                                           \
    for (int i = 0; i < 2; i++)                                                 \
        _Pragma("unroll")                                                       \
        for (int j = 0; j < 8; j++)                                             \
            _Pragma("unroll")                                                   \
            for (int l = 0; l < 4; l++) acc[i][j][l] = 0.f;

#define EPI_F32(Cp, ldc, alpha)                                                 \
    _Pragma("unroll")                                                           \
    for (int mt = 0; mt < 2; mt++)                                              \
        _Pragma("unroll")                                                       \
        for (int nt = 0; nt < 8; nt++) {                                        \
            int r = rowA0 + m0 + mt * 16 + g;                                   \
            int cix = col0 + n0 + nt * 8 + tig * 2;                             \
            *(float2*)((Cp) + (size_t)r * (ldc) + cix) =                        \
                make_float2(acc[mt][nt][0] * (alpha), acc[mt][nt][1] * (alpha));\
            *(float2*)((Cp) + (size_t)(r + 8) * (ldc) + cix) =                  \
                make_float2(acc[mt][nt][2] * (alpha), acc[mt][nt][3] * (alpha));\
        }

#define GEMM_SMEM 81920

// ---------------- kernel: pool + RMS norm + GELU, split-bf16 out --------------
__global__ __launch_bounds__(256) void pool_norm_kernel(
    const float* __restrict__ x, const float* __restrict__ norm_w)
{
    int bid = blockIdx.x;
    int b = bid >> 9, p = bid & 511;
    int tid = threadIdx.x;

    const float* xrow = x + ((size_t)b * S_ + (size_t)p * 16) * C_;
    float xp[6];
#pragma unroll
    for (int j = 0; j < 6; j++) xp[j] = 0.f;
    for (int r = 0; r < 16; r++) {
        const float* xr = xrow + (size_t)r * C_;
#pragma unroll
        for (int j = 0; j < 6; j++) xp[j] += xr[tid + j * 256];
    }
    float ssq = 0.f;
#pragma unroll
    for (int j = 0; j < 6; j++) { xp[j] *= (1.f / 16.f); ssq += xp[j] * xp[j]; }

    __shared__ float red[256];
    red[tid] = ssq;
    __syncthreads();
    for (int s = 128; s > 0; s >>= 1) {
        if (tid < s) red[tid] += red[tid + s];
        __syncthreads();
    }
    float scale = 1.f / sqrtf(red[0] * (1.f / (float)C_) + 1e-8f);

    size_t base = (size_t)bid * C_;
#pragma unroll
    for (int j = 0; j < 6; j++) {
        int ch = tid + j * 256;
        float v = xp[j] * scale * norm_w[ch];
        float gv = v * 0.5f * (1.f + erff(v * 0.70710678118654752f));
        bf16 h = __float2bfloat16(v);
        g_xnh[base + ch] = h;
        g_xnl[base + ch] = __float2bfloat16(v - __bfloat162float(h));
        bf16 gh = __float2bfloat16(gv);
        g_xgh[base + ch] = gh;
        g_xgl[base + ch] = __float2bfloat16(gv - __bfloat162float(gh));
    }
}

// ---------------- kernel: pos features @ Wpos + bpos, split-bf16 out ----------
__global__ __launch_bounds__(128) void pos_kernel(
    const float* __restrict__ Wpos, const float* __restrict__ bpos)
{
    int d   = blockIdx.x;
    int tid = threadIdx.x;
    __shared__ float feat[32];

    int rel = d - P_;
    if (tid < 16) {
        double geo = exp((double)tid * (log(497.0) / 16.0));
        float center = (float)tid + (float)geo;
        float oh = (center > fabsf((float)rel)) ? 1.f : 0.f;
        float sg = (rel > 0) ? 1.f : ((rel < 0) ? -1.f : 0.f);
        feat[tid]      = oh;
        feat[tid + 16] = oh * sg;
    }
    __syncthreads();

    float f[32];
#pragma unroll
    for (int c = 0; c < 32; c++) f[c] = feat[c];

    for (int n = tid; n < HF; n += 128) {
        float acc = bpos[n];
#pragma unroll
        for (int c = 0; c < 32; c++) acc += f[c] * Wpos[c * HF + n];
        bf16 h = __float2bfloat16(acc);
        g_posh[(size_t)d * HF + n] = h;
        g_posl[(size_t)d * HF + n] = __float2bfloat16(acc - __bfloat162float(h));
    }
}

// ---------------- kernel: rel-bias tables Bias[sel][h][d] = 0.25*rb·pos -------
__global__ __launch_bounds__(256) void bias_kernel(
    const float* __restrict__ qrb, const float* __restrict__ krb)
{
    int d = blockIdx.x;
    int lane = threadIdx.x & 31, w = threadIdx.x >> 5;
    for (int h = w; h < H_; h += 8) {
        float sq = 0.f, sk = 0.f;
        size_t pb = (size_t)d * HF + h * F_;
        for (int c = lane; c < F_; c += 32) {
            float pv = __bfloat162float(g_posh[pb + c])
                     + __bfloat162float(g_posl[pb + c]);
            sq += qrb[h * F_ + c] * pv;
            sk += krb[h * F_ + c] * pv;
        }
#pragma unroll
        for (int o = 16; o; o >>= 1) {
            sq += __shfl_xor_sync(0xffffffffu, sq, o);
            sk += __shfl_xor_sync(0xffffffffu, sk, o);
        }
        if (lane == 0) {
            g_bias[h * P2 + d]             = 0.25f * sq;
            g_bias[H_ * P2 + h * P2 + d]   = 0.25f * sk;
        }
    }
}

// ---------------- kernel: weight transpose-convert W[K,N] -> T[N,K] split ------
__global__ __launch_bounds__(256) void wconv_kernel(
    const float* __restrict__ W, bf16* __restrict__ Th, bf16* __restrict__ Tl,
    int K, int N)
{
    __shared__ float t[32][33];
    int nt0 = blockIdx.x * 32, kt0 = blockIdx.y * 32;
    int tx = threadIdx.x & 31, ty = threadIdx.x >> 5;
#pragma unroll
    for (int i = 0; i < 4; i++)
        t[ty + i * 8][tx] = W[(size_t)(kt0 + ty + i * 8) * N + nt0 + tx];
    __syncthreads();
#pragma unroll
    for (int i = 0; i < 4; i++) {
        int n = nt0 + ty + i * 8, k = kt0 + tx;
        float v = t[tx][ty + i * 8];
        bf16 h = __float2bfloat16(v);
        Th[(size_t)n * K + k] = h;
        Tl[(size_t)n * K + k] = __float2bfloat16(v - __bfloat162float(h));
    }
}

// ---------------- kernel: projection GEMM (q/k), split-bf16 out ---------------
__global__ __launch_bounds__(256, 2) void proj_gemm(
    const bf16* __restrict__ Ah, const bf16* __restrict__ Al,
    const bf16* __restrict__ Bh, const bf16* __restrict__ Bl,
    bf16* __restrict__ Oh, bf16* __restrict__ Ol)
{
    GEMM_PREAMBLE
    int rowA0 = blockIdx.y * 128, col0 = blockIdx.x * 128;
    GEMM_MAIN(Ah, Al, Bh, Bl, C_, C_, 0, C_ / 32);

    uint32_t* oh = (uint32_t*)Oh;
    uint32_t* ol = (uint32_t*)Ol;
#pragma unroll
    for (int mt = 0; mt < 2; mt++)
#pragma unroll
        for (int nt = 0; nt < 8; nt++) {
            int r = rowA0 + m0 + mt * 16 + g;
            int n = col0 + n0 + nt * 8 + tig * 2;
            uint32_t hw, lw;
            size_t ix0 = ((size_t)r * HF + n) >> 1;
            size_t ix1 = ((size_t)(r + 8) * HF + n) >> 1;
            split2(acc[mt][nt][0], acc[mt][nt][1], hw, lw);
            oh[ix0] = hw; ol[ix0] = lw;
            split2(acc[mt][nt][2], acc[mt][nt][3], hw, lw);
            oh[ix1] = hw; ol[ix1] = lw;
        }
}

// ---------------- kernel: yq/yk GEMM, split-K x4, both outputs ----------------
__global__ __launch_bounds__(256, 2) void y_gemm(
    const bf16* __restrict__ Ah, const bf16* __restrict__ Al,
    const bf16* __restrict__ B0h, const bf16* __restrict__ B0l,
    const bf16* __restrict__ B1h, const bf16* __restrict__ B1l,
    float* __restrict__ ypart)
{
    GEMM_PREAMBLE
    int z = blockIdx.z;
    const bf16* Bh = (z >= 4) ? B1h : B0h;
    const bf16* Bl = (z >= 4) ? B1l : B0l;
    int kb = (z & 3) * 384;
    int rowA0 = blockIdx.y * 128, col0 = 0;
    GEMM_MAIN(Ah, Al, Bh, Bl, C_, C_, kb, 12);
    float* C = ypart + (size_t)z * M_ * F_;
    EPI_F32(C, F_, 1.0f)
}

// ---------------- kernel: batched relative GEMM (QK / Qp / Kp) ----------------
// band!=0: grid.x=20 maps to the needed (q,d) tile band; bias added per column.
__global__ __launch_bounds__(256, 2) void rel_gemm(
    const bf16* __restrict__ Ahb, const bf16* __restrict__ Alb,
    const bf16* __restrict__ Bhb, const bf16* __restrict__ Blb,
    float* __restrict__ Cbase, const float* __restrict__ biasT,
    int N, int bInB, int band, float alpha)
{
    GEMM_PREAMBLE
    int z = blockIdx.z, b = z >> 5, h = z & 31;
    int tx, ty;
    if (band) { int i = blockIdx.x; ty = i / 5; tx = 3 - ty + (i % 5); }
    else      { tx = blockIdx.x; ty = blockIdx.y; }
    const bf16* Ah = Ahb + (size_t)b * P_ * HF + h * F_;
    const bf16* Al = Alb + (size_t)b * P_ * HF + h * F_;
    const bf16* Bh = Bhb + (bInB ? (size_t)b * P_ * HF : 0) + h * F_;
    const bf16* Bl = Blb + (bInB ? (size_t)b * P_ * HF : 0) + h * F_;
    float* C = Cbase + (size_t)z * P_ * N;
    int rowA0 = ty * 128, col0 = tx * 128;
    GEMM_MAIN(Ah, Al, Bh, Bl, HF, HF, 0, 4);

    const float* bp = biasT ? (biasT + (size_t)h * N) : (const float*)0;
#pragma unroll
    for (int mt = 0; mt < 2; mt++)
#pragma unroll
        for (int nt = 0; nt < 8; nt++) {
            int r = rowA0 + m0 + mt * 16 + g;
            int cix = col0 + n0 + nt * 8 + tig * 2;
            float b0 = 0.f, b1 = 0.f;
            if (bp) { float2 v = *(const float2*)(bp + cix); b0 = v.x; b1 = v.y; }
            *(float2*)(C + (size_t)r * N + cix) =
                make_float2(acc[mt][nt][0] * alpha + b0, acc[mt][nt][1] * alpha + b1);
            *(float2*)(C + (size_t)(r + 8) * N + cix) =
                make_float2(acc[mt][nt][2] * alpha + b0, acc[mt][nt][3] * alpha + b1);
        }
}

// ---------------- kernel: fused gather + a@Wout epilogue ----------------------
#define A_QSTRIDE 1057
#define A_KSTRIDE 33
#define SMEM_FINAL ((32 * A_QSTRIDE + 2 * 32 * 128) * 4)
#define M128 (M_ * F_)

__global__ __launch_bounds__(256) void final_kernel(
    const float* __restrict__ QK, const float* __restrict__ Qp,
    const float* __restrict__ Kp, const float* __restrict__ ypart,
    const float* __restrict__ Wout, const float* __restrict__ bout,
    float* __restrict__ out)
{
    extern __shared__ float smem[];
    float* a_s  = smem;
    float* yq_s = smem + 32 * A_QSTRIDE;
    float* yk_s = yq_s + 32 * 128;

    int b  = blockIdx.z;
    int qt = blockIdx.y * 32;
    int kt = blockIdx.x * 32;
    int tid = threadIdx.x;

    for (int i = tid; i < 32 * 128; i += 256) {
        int q = i >> 7, f = i & 127;
        size_t rq = ((size_t)(b * P_ + qt + q)) * F_ + f;
        size_t rk = ((size_t)(b * P_ + kt + q)) * F_ + f;
        float vq = 0.f, vk = 0.f;
#pragma unroll
        for (int s = 0; s < 4; s++) {
            vq += ypart[(size_t)s * M128 + rq];
            vk += ypart[(size_t)(4 + s) * M128 + rk];
        }
        yq_s[i] = vq;
        yk_s[i] = vk;
    }

    for (int i = tid; i < 32 * 32 * 32; i += 256) {
        int h = i >> 10, q = (i >> 5) & 31, k = i & 31;
        int gq = qt + q, gk = kt + k;
        size_t zb = (size_t)(b * 32 + h);
        float v = QK[(zb * P_ + gq) * P_ + gk]
                + Qp[(zb * P_ + gq) * P2 + (P_ + gk - gq)];
        a_s[q * A_QSTRIDE + k * A_KSTRIDE + h] = v;
    }
    __syncthreads();

    for (int i = tid; i < 32 * 32 * 32; i += 256) {
        int h = i >> 10, k = (i >> 5) & 31, q = i & 31;
        int gq = qt + q, gk = kt + k;
        size_t zb = (size_t)(b * 32 + h);
        a_s[q * A_QSTRIDE + k * A_KSTRIDE + h] +=
            Kp[(zb * P_ + gk) * P2 + (P_ + gq - gk)];
    }
    __syncthreads();

    int lane = tid & 31, warp = tid >> 5;
    float w[32][4];
#pragma unroll
    for (int h = 0; h < 32; h++)
#pragma unroll
        for (int j = 0; j < 4; j++) w[h][j] = Wout[h * F_ + lane + j * 32];
    float bo[4];
#pragma unroll
    for (int j = 0; j < 4; j++) bo[j] = bout[lane + j * 32];

    for (int p = warp; p < 1024; p += 8) {
        int q = p >> 5, k = p & 31;
        const float* ap = a_s + q * A_QSTRIDE + k * A_KSTRIDE;
        float acc[4];
#pragma unroll
        for (int j = 0; j < 4; j++)
            acc[j] = bo[j] + yq_s[q * 128 + lane + j * 32]
                           + yk_s[k * 128 + lane + j * 32];
#pragma unroll
        for (int h = 0; h < 32; h++) {
            float ah = ap[h];
#pragma unroll
            for (int j = 0; j < 4; j++) acc[j] += ah * w[h][j];
        }
        float* orow = out + (((size_t)(b * P_) + qt + q) * P_ + kt + k) * F_ + lane;
#pragma unroll
        for (int j = 0; j < 4; j++) orow[j * 32] = acc[j];
    }
}

// ---------------- launch ------------------------------------------------------
extern "C" void kernel_launch(void* const* d_in, const int* in_sizes, int n_in,
                              void* d_out, int out_size)
{
    const float* x        = (const float*)d_in[0];
    const float* norm_w   = (const float*)d_in[1];
    const float* Wq       = (const float*)d_in[2];
    const float* Wk       = (const float*)d_in[3];
    const float* Wpos     = (const float*)d_in[4];
    const float* bpos     = (const float*)d_in[5];
    const float* q_r_bias = (const float*)d_in[6];
    const float* k_r_bias = (const float*)d_in[7];
    const float* Wyq      = (const float*)d_in[8];
    const float* Wyk      = (const float*)d_in[9];
    const float* Wout     = (const float*)d_in[10];
    const float* bout     = (const float*)d_in[11];
    float* out = (float*)d_out;

    bf16 *p_xnh, *p_xnl, *p_xgh, *p_xgl;
    bf16 *p_wqth, *p_wqtl, *p_wkth, *p_wktl, *p_wyqh, *p_wyql, *p_wykh, *p_wykl;
    bf16 *p_posh, *p_posl, *p_qh, *p_ql, *p_kh, *p_kl;
    float *p_bias, *p_ypart, *p_QK, *p_Qp, *p_Kp;
    cudaGetSymbolAddress((void**)&p_xnh,  g_xnh);
    cudaGetSymbolAddress((void**)&p_xnl,  g_xnl);
    cudaGetSymbolAddress((void**)&p_xgh,  g_xgh);
    cudaGetSymbolAddress((void**)&p_xgl,  g_xgl);
    cudaGetSymbolAddress((void**)&p_wqth, g_wqth);
    cudaGetSymbolAddress((void**)&p_wqtl, g_wqtl);
    cudaGetSymbolAddress((void**)&p_wkth, g_wkth);
    cudaGetSymbolAddress((void**)&p_wktl, g_wktl);
    cudaGetSymbolAddress((void**)&p_wyqh, g_wyqh);
    cudaGetSymbolAddress((void**)&p_wyql, g_wyql);
    cudaGetSymbolAddress((void**)&p_wykh, g_wykh);
    cudaGetSymbolAddress((void**)&p_wykl, g_wykl);
    cudaGetSymbolAddress((void**)&p_posh, g_posh);
    cudaGetSymbolAddress((void**)&p_posl, g_posl);
    cudaGetSymbolAddress((void**)&p_qh,   g_qh);
    cudaGetSymbolAddress((void**)&p_ql,   g_ql);
    cudaGetSymbolAddress((void**)&p_kh,   g_kh);
    cudaGetSymbolAddress((void**)&p_kl,   g_kl);
    cudaGetSymbolAddress((void**)&p_bias, g_bias);
    cudaGetSymbolAddress((void**)&p_ypart, g_ypart);
    cudaGetSymbolAddress((void**)&p_QK,   g_QK);
    cudaGetSymbolAddress((void**)&p_Qp,   g_Qp);
    cudaGetSymbolAddress((void**)&p_Kp,   g_Kp);

    cudaFuncSetAttribute(proj_gemm, cudaFuncAttributeMaxDynamicSharedMemorySize, GEMM_SMEM);
    cudaFuncSetAttribute(y_gemm,    cudaFuncAttributeMaxDynamicSharedMemorySize, GEMM_SMEM);
    cudaFuncSetAttribute(rel_gemm,  cudaFuncAttributeMaxDynamicSharedMemorySize, GEMM_SMEM);
    cudaFuncSetAttribute(final_kernel, cudaFuncAttributeMaxDynamicSharedMemorySize, SMEM_FINAL);

    // prep
    pool_norm_kernel<<<1024, 256>>>(x, norm_w);
    pos_kernel<<<1024, 128>>>(Wpos, bpos);
    bias_kernel<<<1024, 256>>>(q_r_bias, k_r_bias);
    wconv_kernel<<<dim3(128, 48), 256>>>(Wq,  p_wqth, p_wqtl, C_, HF);
    wconv_kernel<<<dim3(128, 48), 256>>>(Wk,  p_wkth, p_wktl, C_, HF);
    wconv_kernel<<<dim3(4, 48),   256>>>(Wyq, p_wyqh, p_wyql, C_, F_);
    wconv_kernel<<<dim3(4, 48),   256>>>(Wyk, p_wykh, p_wykl, C_, F_);

    // projections
    proj_gemm<<<dim3(32, 8), 256, GEMM_SMEM>>>(
        p_xnh, p_xnl, p_wqth, p_wqtl, p_qh, p_ql);
    proj_gemm<<<dim3(32, 8), 256, GEMM_SMEM>>>(
        p_xnh, p_xnl, p_wkth, p_wktl, p_kh, p_kl);
    y_gemm<<<dim3(1, 8, 8), 256, GEMM_SMEM>>>(
        p_xgh, p_xgl, p_wyqh, p_wyql, p_wykh, p_wykl, p_ypart);

    // relative GEMMs (Qp/Kp band-trimmed: 20 of 32 tiles)
    rel_gemm<<<dim3(4, 4, 64), 256, GEMM_SMEM>>>(
        p_qh, p_ql, p_kh, p_kl, p_QK, (const float*)0, P_, 1, 0, 1.0f);
    rel_gemm<<<dim3(20, 1, 64), 256, GEMM_SMEM>>>(
        p_qh, p_ql, p_posh, p_posl, p_Qp, p_bias,            P2, 0, 1, 0.25f);
    rel_gemm<<<dim3(20, 1, 64), 256, GEMM_SMEM>>>(
        p_kh, p_kl, p_posh, p_posl, p_Kp, p_bias + H_ * P2,  P2, 0, 1, 0.25f);

    final_kernel<<<dim3(16, 16, 2), 256, SMEM_FINAL>>>(
        p_QK, p_Qp, p_Kp, p_ypart, Wout, bout, out);
}

// round 5
// speedup vs baseline: 2.8004x; 1.1957x over previous
#include <cuda_runtime.h>
#include <cuda_fp16.h>
#include <math.h>
#include <stdint.h>

typedef __half fp16;

#define B_   2
#define S_   8192
#define C_   1536
#define P_   512
#define H_   32
#define F_   128
#define HF   4096
#define P2   1024
#define M_   1024     // B_*P_

// ---------------- scratch (device globals) ------------------------------------
__device__ __align__(16) fp16 g_xnh[M_ * C_];              // A-side: hi only
__device__ __align__(16) fp16 g_xgh[M_ * C_];
__device__ __align__(16) fp16 g_wqth[HF * C_], g_wqtl[HF * C_];
__device__ __align__(16) fp16 g_wkth[HF * C_], g_wktl[HF * C_];
__device__ __align__(16) fp16 g_wyqh[F_ * C_], g_wyql[F_ * C_];
__device__ __align__(16) fp16 g_wykh[F_ * C_], g_wykl[F_ * C_];
__device__ __align__(16) fp16 g_posh[P2 * HF], g_posl[P2 * HF];
__device__ __align__(16) fp16 g_qh [M_ * HF];              // q: A only -> hi
__device__ __align__(16) fp16 g_kh [M_ * HF], g_kl[M_ * HF]; // k: B of QK -> hi+lo
__device__ float g_bias [2 * H_ * P2];
__device__ float g_ypart[8 * M_ * F_];
__device__ float g_QK [(size_t)B_ * H_ * P_ * P_];
__device__ float g_Qp [(size_t)B_ * H_ * P_ * P2];
__device__ float g_Kp [(size_t)B_ * H_ * P_ * P2];

// ---------------- helpers ------------------------------------------------------
__device__ __forceinline__ void hsplit2(float x, float y, uint32_t& hw, uint32_t& lw)
{
    __half hx = __float2half(x);
    __half hy = __float2half(y);
    __half lx = __float2half(x - __half2float(hx));
    __half ly = __float2half(y - __half2float(hy));
    __half2 hp = __halves2half2(hx, hy);
    __half2 lp = __halves2half2(lx, ly);
    hw = *reinterpret_cast<uint32_t*>(&hp);
    lw = *reinterpret_cast<uint32_t*>(&lp);
}

__device__ __forceinline__ void cp16(uint32_t* smem_ptr, const fp16* gptr)
{
    uint32_t s = (uint32_t)__cvta_generic_to_shared(smem_ptr);
    asm volatile("cp.async.cg.shared.global [%0], [%1], 16;\n" :: "r"(s), "l"(gptr));
}

#define MMA_FP16(c, a, b)                                                       \
    asm volatile(                                                               \
        "mma.sync.aligned.m16n8k16.row.col.f32.f16.f16.f32 "                    \
        "{%0,%1,%2,%3}, {%4,%5,%6,%7}, {%8,%9}, {%0,%1,%2,%3};\n"               \
        : "+f"((c)[0]), "+f"((c)[1]), "+f"((c)[2]), "+f"((c)[3])                \
        : "r"((a)[0]), "r"((a)[1]), "r"((a)[2]), "r"((a)[3]),                   \
          "r"((b)[0]), "r"((b)[1]))

#define LDSM4(d0, d1, d2, d3, a)                                                \
    asm volatile(                                                               \
        "ldmatrix.sync.aligned.m8n8.x4.shared.b16 {%0,%1,%2,%3}, [%4];\n"       \
        : "=r"(d0), "=r"(d1), "=r"(d2), "=r"(d3) : "r"(a))

// one k16 sub-step: A-hi x (B-hi + B-lo)  -> 10 LDSM.x4 + 32 MMAs per warp
#define FRAG_LDSM(sst, j0)                                                      \
    do {                                                                        \
        uint32_t ah[2][4], bh[8][2], bl[8][2];                                  \
        _Pragma("unroll")                                                       \
        for (int mt = 0; mt < 2; mt++) {                                        \
            uint32_t aa = (sst) + aoff + mt * 1280u + (j0) * 4u;                \
            LDSM4(ah[mt][0], ah[mt][1], ah[mt][2], ah[mt][3], aa);              \
        }                                                                       \
        _Pragma("unroll")                                                       \
        for (int tp = 0; tp < 4; tp++) {                                        \
            uint32_t ba = (sst) + boff + tp * 1280u + (j0) * 4u + 10240u;       \
            LDSM4(bh[2*tp][0], bh[2*tp+1][0], bh[2*tp][1], bh[2*tp+1][1], ba);  \
            LDSM4(bl[2*tp][0], bl[2*tp+1][0], bl[2*tp][1], bl[2*tp+1][1],       \
                  ba + 10240u);                                                 \
        }                                                                       \
        _Pragma("unroll")                                                       \
        for (int mt = 0; mt < 2; mt++)                                          \
            _Pragma("unroll")                                                   \
            for (int nt = 0; nt < 8; nt++) {                                    \
                MMA_FP16(acc[mt][nt], ah[mt], bh[nt]);                          \
                MMA_FP16(acc[mt][nt], ah[mt], bl[nt]);                          \
            }                                                                   \
    } while (0)

// stage = [Ah 10240B][Bh 10240B][Bl 10240B] = 30720B; 3 stages
#define LOAD_STAGE(s, kpos, Ah, Bh, Bl, lda, ldb)                               \
    {                                                                           \
        uint32_t* sb = sm + (s) * 7680;                                         \
        _Pragma("unroll")                                                       \
        for (int ci = 0; ci < 2; ci++) {                                        \
            int qq = tid + ci * 256;                                            \
            int rw = qq >> 2, cc = qq & 3;                                      \
            uint32_t so = rw * 20 + cc * 4;                                     \
            size_t ga = (size_t)(rowA0 + rw) * (lda) + (kpos) + cc * 8;         \
            size_t gb = (size_t)(col0 + rw) * (ldb) + (kpos) + cc * 8;          \
            cp16(sb + so,        (Ah) + ga);                                    \
            cp16(sb + 2560 + so, (Bh) + gb);                                    \
            cp16(sb + 5120 + so, (Bl) + gb);                                    \
        }                                                                       \
    }

// 3-stage cp.async pipeline (requires nk >= 2)
#define GEMM_MAIN(Ah, Bh, Bl, lda, ldb, kb, nk)                                 \
    {                                                                           \
        LOAD_STAGE(0, (kb), Ah, Bh, Bl, lda, ldb);                              \
        asm volatile("cp.async.commit_group;\n");                               \
        LOAD_STAGE(1, (kb) + 32, Ah, Bh, Bl, lda, ldb);                         \
        asm volatile("cp.async.commit_group;\n");                               \
        for (int it = 0; it < (nk); it++) {                                     \
            if (it + 2 < (nk)) asm volatile("cp.async.wait_group 1;\n");        \
            else               asm volatile("cp.async.wait_group 0;\n");        \
            __syncthreads();                                                    \
            uint32_t sst = smb + (uint32_t)((it % 3) * 30720);                  \
            FRAG_LDSM(sst, 0);                                                  \
            if (it + 2 < (nk)) {                                                \
                LOAD_STAGE((it + 2) % 3, (kb) + (it + 2) * 32,                  \
                           Ah, Bh, Bl, lda, ldb);                               \
                asm volatile("cp.async.commit_group;\n");                       \
            }                                                                   \
            FRAG_LDSM(sst, 8);                                                  \
        }                                                                       \
    }

#define GEMM_PREAMBLE                                                           \
    extern __shared__ uint32_t sm[];                                            \
    uint32_t smb = (uint32_t)__cvta_generic_to_shared(sm);                      \
    int tid = threadIdx.x;                                                      \
    int warp = tid >> 5, lane = tid & 31;                                       \
    int g = lane >> 2, tig = lane & 3;                                          \
    int lr = lane & 15, lh = lane >> 4;                                         \
    int m0 = (warp >> 1) * 32, n0 = (warp & 1) * 64;                            \
    uint32_t aoff = ((m0 + lr) * 20 + lh * 4) * 4;                              \
    uint32_t boff = ((n0 + lr) * 20 + lh * 4) * 4;                              \
    float acc[2][8][4];                                                         \
    _Pragma("unroll")                                                           \
    for (int i = 0; i < 2; i++)                                                 \
        _Pragma("unroll")                                                       \
        for (int j = 0; j < 8; j++)                                             \
            _Pragma("unroll")                                                   \
            for (int l = 0; l < 4; l++) acc[i][j][l] = 0.f;

#define EPI_F32(Cp, ldc, alpha)                                                 \
    _Pragma("unroll")                                                           \
    for (int mt = 0; mt < 2; mt++)                                              \
        _Pragma("unroll")                                                       \
        for (int nt = 0; nt < 8; nt++) {                                        \
            int r = rowA0 + m0 + mt * 16 + g;                                   \
            int cix = col0 + n0 + nt * 8 + tig * 2;                             \
            *(float2*)((Cp) + (size_t)r * (ldc) + cix) =                        \
                make_float2(acc[mt][nt][0] * (alpha), acc[mt][nt][1] * (alpha));\
            *(float2*)((Cp) + (size_t)(r + 8) * (ldc) + cix) =                  \
                make_float2(acc[mt][nt][2] * (alpha), acc[mt][nt][3] * (alpha));\
        }

#define GEMM_SMEM 92160

// ---------------- kernel: pool + RMS norm + GELU (hi fp16 out) ----------------
__global__ __launch_bounds__(256) void pool_norm_kernel(
    const float* __restrict__ x, const float* __restrict__ norm_w)
{
    int bid = blockIdx.x;
    int b = bid >> 9, p = bid & 511;
    int tid = threadIdx.x;

    const float* xrow = x + ((size_t)b * S_ + (size_t)p * 16) * C_;
    float xp[6];
#pragma unroll
    for (int j = 0; j < 6; j++) xp[j] = 0.f;
    for (int r = 0; r < 16; r++) {
        const float* xr = xrow + (size_t)r * C_;
#pragma unroll
        for (int j = 0; j < 6; j++) xp[j] += xr[tid + j * 256];
    }
    float ssq = 0.f;
#pragma unroll
    for (int j = 0; j < 6; j++) { xp[j] *= (1.f / 16.f); ssq += xp[j] * xp[j]; }

    __shared__ float red[256];
    red[tid] = ssq;
    __syncthreads();
    for (int s = 128; s > 0; s >>= 1) {
        if (tid < s) red[tid] += red[tid + s];
        __syncthreads();
    }
    float scale = 1.f / sqrtf(red[0] * (1.f / (float)C_) + 1e-8f);

    size_t base = (size_t)bid * C_;
#pragma unroll
    for (int j = 0; j < 6; j++) {
        int ch = tid + j * 256;
        float v = xp[j] * scale * norm_w[ch];
        float gv = v * 0.5f * (1.f + erff(v * 0.70710678118654752f));
        g_xnh[base + ch] = __float2half(v);
        g_xgh[base + ch] = __float2half(gv);
    }
}

// ---------------- kernel: pos features @ Wpos + bpos (split fp16 out) ---------
__global__ __launch_bounds__(128) void pos_kernel(
    const float* __restrict__ Wpos, const float* __restrict__ bpos)
{
    int d   = blockIdx.x;
    int tid = threadIdx.x;
    __shared__ float feat[32];

    int rel = d - P_;
    if (tid < 16) {
        double geo = exp((double)tid * (log(497.0) / 16.0));
        float center = (float)tid + (float)geo;
        float oh = (center > fabsf((float)rel)) ? 1.f : 0.f;
        float sg = (rel > 0) ? 1.f : ((rel < 0) ? -1.f : 0.f);
        feat[tid]      = oh;
        feat[tid + 16] = oh * sg;
    }
    __syncthreads();

    float f[32];
#pragma unroll
    for (int c = 0; c < 32; c++) f[c] = feat[c];

    for (int n = tid; n < HF; n += 128) {
        float acc = bpos[n];
#pragma unroll
        for (int c = 0; c < 32; c++) acc += f[c] * Wpos[c * HF + n];
        __half h = __float2half(acc);
        g_posh[(size_t)d * HF + n] = h;
        g_posl[(size_t)d * HF + n] = __float2half(acc - __half2float(h));
    }
}

// ---------------- kernel: rel-bias tables Bias[sel][h][d] = 0.25*rb·pos -------
__global__ __launch_bounds__(256) void bias_kernel(
    const float* __restrict__ qrb, const float* __restrict__ krb)
{
    int d = blockIdx.x;
    int lane = threadIdx.x & 31, w = threadIdx.x >> 5;
    for (int h = w; h < H_; h += 8) {
        float sq = 0.f, sk = 0.f;
        size_t pb = (size_t)d * HF + h * F_;
        for (int c = lane; c < F_; c += 32) {
            float pv = __half2float(g_posh[pb + c]) + __half2float(g_posl[pb + c]);
            sq += qrb[h * F_ + c] * pv;
            sk += krb[h * F_ + c] * pv;
        }
#pragma unroll
        for (int o = 16; o; o >>= 1) {
            sq += __shfl_xor_sync(0xffffffffu, sq, o);
            sk += __shfl_xor_sync(0xffffffffu, sk, o);
        }
        if (lane == 0) {
            g_bias[h * P2 + d]           = 0.25f * sq;
            g_bias[H_ * P2 + h * P2 + d] = 0.25f * sk;
        }
    }
}

// ---------------- kernel: weight transpose-convert W[K,N] -> T[N,K] split -----
__global__ __launch_bounds__(256) void wconv_kernel(
    const float* __restrict__ W, fp16* __restrict__ Th, fp16* __restrict__ Tl,
    int K, int N)
{
    __shared__ float t[32][33];
    int nt0 = blockIdx.x * 32, kt0 = blockIdx.y * 32;
    int tx = threadIdx.x & 31, ty = threadIdx.x >> 5;
#pragma unroll
    for (int i = 0; i < 4; i++)
        t[ty + i * 8][tx] = W[(size_t)(kt0 + ty + i * 8) * N + nt0 + tx];
    __syncthreads();
#pragma unroll
    for (int i = 0; i < 4; i++) {
        int n = nt0 + ty + i * 8, k = kt0 + tx;
        float v = t[tx][ty + i * 8];
        __half h = __float2half(v);
        Th[(size_t)n * K + k] = h;
        Tl[(size_t)n * K + k] = __float2half(v - __half2float(h));
    }
}

// ---------------- kernel: projection GEMM (q/k) -------------------------------
// Ol may be null (q needs hi only; k needs hi+lo for its B role in QK)
__global__ __launch_bounds__(256, 2) void proj_gemm(
    const fp16* __restrict__ Ah,
    const fp16* __restrict__ Bh, const fp16* __restrict__ Bl,
    fp16* __restrict__ Oh, fp16* __restrict__ Ol)
{
    GEMM_PREAMBLE
    int rowA0 = blockIdx.y * 128, col0 = blockIdx.x * 128;
    GEMM_MAIN(Ah, Bh, Bl, C_, C_, 0, C_ / 32);

    uint32_t* oh = (uint32_t*)Oh;
    uint32_t* ol = (uint32_t*)Ol;
#pragma unroll
    for (int mt = 0; mt < 2; mt++)
#pragma unroll
        for (int nt = 0; nt < 8; nt++) {
            int r = rowA0 + m0 + mt * 16 + g;
            int n = col0 + n0 + nt * 8 + tig * 2;
            uint32_t hw, lw;
            size_t ix0 = ((size_t)r * HF + n) >> 1;
            size_t ix1 = ((size_t)(r + 8) * HF + n) >> 1;
            hsplit2(acc[mt][nt][0], acc[mt][nt][1], hw, lw);
            oh[ix0] = hw;
            if (ol) ol[ix0] = lw;
            hsplit2(acc[mt][nt][2], acc[mt][nt][3], hw, lw);
            oh[ix1] = hw;
            if (ol) ol[ix1] = lw;
        }
}

// ---------------- kernel: yq/yk GEMM, split-K x4 -------------------------------
__global__ __launch_bounds__(256, 2) void y_gemm(
    const fp16* __restrict__ Ah,
    const fp16* __restrict__ B0h, const fp16* __restrict__ B0l,
    const fp16* __restrict__ B1h, const fp16* __restrict__ B1l,
    float* __restrict__ ypart)
{
    GEMM_PREAMBLE
    int z = blockIdx.z;
    const fp16* Bh = (z >= 4) ? B1h : B0h;
    const fp16* Bl = (z >= 4) ? B1l : B0l;
    int kb = (z & 3) * 384;
    int rowA0 = blockIdx.y * 128, col0 = 0;
    GEMM_MAIN(Ah, Bh, Bl, C_, C_, kb, 12);
    float* C = ypart + (size_t)z * M_ * F_;
    EPI_F32(C, F_, 1.0f)
}

// ---------------- kernel: batched relative GEMM (QK / Qp / Kp) ----------------
__global__ __launch_bounds__(256, 2) void rel_gemm(
    const fp16* __restrict__ Ahb,
    const fp16* __restrict__ Bhb, const fp16* __restrict__ Blb,
    float* __restrict__ Cbase, const float* __restrict__ biasT,
    int N, int bInB, int band, float alpha)
{
    GEMM_PREAMBLE
    int z = blockIdx.z, b = z >> 5, h = z & 31;
    int tx, ty;
    if (band) { int i = blockIdx.x; ty = i / 5; tx = 3 - ty + (i % 5); }
    else      { tx = blockIdx.x; ty = blockIdx.y; }
    const fp16* Ah = Ahb + (size_t)b * P_ * HF + h * F_;
    const fp16* Bh = Bhb + (bInB ? (size_t)b * P_ * HF : 0) + h * F_;
    const fp16* Bl = Blb + (bInB ? (size_t)b * P_ * HF : 0) + h * F_;
    float* C = Cbase + (size_t)z * P_ * N;
    int rowA0 = ty * 128, col0 = tx * 128;
    GEMM_MAIN(Ah, Bh, Bl, HF, HF, 0, 4);

    const float* bp = biasT ? (biasT + (size_t)h * N) : (const float*)0;
#pragma unroll
    for (int mt = 0; mt < 2; mt++)
#pragma unroll
        for (int nt = 0; nt < 8; nt++) {
            int r = rowA0 + m0 + mt * 16 + g;
            int cix = col0 + n0 + nt * 8 + tig * 2;
            float b0 = 0.f, b1 = 0.f;
            if (bp) { float2 v = *(const float2*)(bp + cix); b0 = v.x; b1 = v.y; }
            *(float2*)(C + (size_t)r * N + cix) =
                make_float2(acc[mt][nt][0] * alpha + b0, acc[mt][nt][1] * alpha + b1);
            *(float2*)(C + (size_t)(r + 8) * N + cix) =
                make_float2(acc[mt][nt][2] * alpha + b0, acc[mt][nt][3] * alpha + b1);
        }
}

// ---------------- kernel: fused gather + a@Wout epilogue ----------------------
#define A_QSTRIDE 1057
#define A_KSTRIDE 33
#define SMEM_FINAL ((32 * A_QSTRIDE + 2 * 32 * 128) * 4)
#define M128 (M_ * F_)

__global__ __launch_bounds__(256) void final_kernel(
    const float* __restrict__ QK, const float* __restrict__ Qp,
    const float* __restrict__ Kp, const float* __restrict__ ypart,
    const float* __restrict__ Wout, const float* __restrict__ bout,
    float* __restrict__ out)
{
    extern __shared__ float smem[];
    float* a_s  = smem;
    float* yq_s = smem + 32 * A_QSTRIDE;
    float* yk_s = yq_s + 32 * 128;

    int b  = blockIdx.z;
    int qt = blockIdx.y * 32;
    int kt = blockIdx.x * 32;
    int tid = threadIdx.x;

    for (int i = tid; i < 32 * 128; i += 256) {
        int q = i >> 7, f = i & 127;
        size_t rq = ((size_t)(b * P_ + qt + q)) * F_ + f;
        size_t rk = ((size_t)(b * P_ + kt + q)) * F_ + f;
        float vq = 0.f, vk = 0.f;
#pragma unroll
        for (int s = 0; s < 4; s++) {
            vq += ypart[(size_t)s * M128 + rq];
            vk += ypart[(size_t)(4 + s) * M128 + rk];
        }
        yq_s[i] = vq;
        yk_s[i] = vk;
    }

    for (int i = tid; i < 32 * 32 * 32; i += 256) {
        int h = i >> 10, q = (i >> 5) & 31, k = i & 31;
        int gq = qt + q, gk = kt + k;
        size_t zb = (size_t)(b * 32 + h);
        float v = QK[(zb * P_ + gq) * P_ + gk]
                + Qp[(zb * P_ + gq) * P2 + (P_ + gk - gq)];
        a_s[q * A_QSTRIDE + k * A_KSTRIDE + h] = v;
    }
    __syncthreads();

    for (int i = tid; i < 32 * 32 * 32; i += 256) {
        int h = i >> 10, k = (i >> 5) & 31, q = i & 31;
        int gq = qt + q, gk = kt + k;
        size_t zb = (size_t)(b * 32 + h);
        a_s[q * A_QSTRIDE + k * A_KSTRIDE + h] +=
            Kp[(zb * P_ + gk) * P2 + (P_ + gq - gk)];
    }
    __syncthreads();

    int lane = tid & 31, warp = tid >> 5;
    float w[32][4];
#pragma unroll
    for (int h = 0; h < 32; h++)
#pragma unroll
        for (int j = 0; j < 4; j++) w[h][j] = Wout[h * F_ + lane + j * 32];
    float bo[4];
#pragma unroll
    for (int j = 0; j < 4; j++) bo[j] = bout[lane + j * 32];

    for (int p = warp; p < 1024; p += 8) {
        int q = p >> 5, k = p & 31;
        const float* ap = a_s + q * A_QSTRIDE + k * A_KSTRIDE;
        float acc[4];
#pragma unroll
        for (int j = 0; j < 4; j++)
            acc[j] = bo[j] + yq_s[q * 128 + lane + j * 32]
                           + yk_s[k * 128 + lane + j * 32];
#pragma unroll
        for (int h = 0; h < 32; h++) {
            float ah = ap[h];
#pragma unroll
            for (int j = 0; j < 4; j++) acc[j] += ah * w[h][j];
        }
        float* orow = out + (((size_t)(b * P_) + qt + q) * P_ + kt + k) * F_ + lane;
#pragma unroll
        for (int j = 0; j < 4; j++) orow[j * 32] = acc[j];
    }
}

// ---------------- launch ------------------------------------------------------
extern "C" void kernel_launch(void* const* d_in, const int* in_sizes, int n_in,
                              void* d_out, int out_size)
{
    const float* x        = (const float*)d_in[0];
    const float* norm_w   = (const float*)d_in[1];
    const float* Wq       = (const float*)d_in[2];
    const float* Wk       = (const float*)d_in[3];
    const float* Wpos     = (const float*)d_in[4];
    const float* bpos     = (const float*)d_in[5];
    const float* q_r_bias = (const float*)d_in[6];
    const float* k_r_bias = (const float*)d_in[7];
    const float* Wyq      = (const float*)d_in[8];
    const float* Wyk      = (const float*)d_in[9];
    const float* Wout     = (const float*)d_in[10];
    const float* bout     = (const float*)d_in[11];
    float* out = (float*)d_out;

    fp16 *p_xnh, *p_xgh;
    fp16 *p_wqth, *p_wqtl, *p_wkth, *p_wktl, *p_wyqh, *p_wyql, *p_wykh, *p_wykl;
    fp16 *p_posh, *p_posl, *p_qh, *p_kh, *p_kl;
    float *p_bias, *p_ypart, *p_QK, *p_Qp, *p_Kp;
    cudaGetSymbolAddress((void**)&p_xnh,  g_xnh);
    cudaGetSymbolAddress((void**)&p_xgh,  g_xgh);
    cudaGetSymbolAddress((void**)&p_wqth, g_wqth);
    cudaGetSymbolAddress((void**)&p_wqtl, g_wqtl);
    cudaGetSymbolAddress((void**)&p_wkth, g_wkth);
    cudaGetSymbolAddress((void**)&p_wktl, g_wktl);
    cudaGetSymbolAddress((void**)&p_wyqh, g_wyqh);
    cudaGetSymbolAddress((void**)&p_wyql, g_wyql);
    cudaGetSymbolAddress((void**)&p_wykh, g_wykh);
    cudaGetSymbolAddress((void**)&p_wykl, g_wykl);
    cudaGetSymbolAddress((void**)&p_posh, g_posh);
    cudaGetSymbolAddress((void**)&p_posl, g_posl);
    cudaGetSymbolAddress((void**)&p_qh,   g_qh);
    cudaGetSymbolAddress((void**)&p_kh,   g_kh);
    cudaGetSymbolAddress((void**)&p_kl,   g_kl);
    cudaGetSymbolAddress((void**)&p_bias, g_bias);
    cudaGetSymbolAddress((void**)&p_ypart, g_ypart);
    cudaGetSymbolAddress((void**)&p_QK,   g_QK);
    cudaGetSymbolAddress((void**)&p_Qp,   g_Qp);
    cudaGetSymbolAddress((void**)&p_Kp,   g_Kp);

    cudaFuncSetAttribute(proj_gemm, cudaFuncAttributeMaxDynamicSharedMemorySize, GEMM_SMEM);
    cudaFuncSetAttribute(y_gemm,    cudaFuncAttributeMaxDynamicSharedMemorySize, GEMM_SMEM);
    cudaFuncSetAttribute(rel_gemm,  cudaFuncAttributeMaxDynamicSharedMemorySize, GEMM_SMEM);
    cudaFuncSetAttribute(final_kernel, cudaFuncAttributeMaxDynamicSharedMemorySize, SMEM_FINAL);

    // prep (ordered so ncu -s 5 captures proj_gemm)
    pool_norm_kernel<<<1024, 256>>>(x, norm_w);          // 0
    pos_kernel<<<1024, 128>>>(Wpos, bpos);               // 1
    bias_kernel<<<1024, 256>>>(q_r_bias, k_r_bias);      // 2
    wconv_kernel<<<dim3(128, 48), 256>>>(Wq, p_wqth, p_wqtl, C_, HF);  // 3
    wconv_kernel<<<dim3(128, 48), 256>>>(Wk, p_wkth, p_wktl, C_, HF);  // 4

    // 5: profiled launch
    proj_gemm<<<dim3(32, 8), 256, GEMM_SMEM>>>(
        p_xnh, p_wqth, p_wqtl, p_qh, (fp16*)0);
    proj_gemm<<<dim3(32, 8), 256, GEMM_SMEM>>>(
        p_xnh, p_wkth, p_wktl, p_kh, p_kl);

    wconv_kernel<<<dim3(4, 48), 256>>>(Wyq, p_wyqh, p_wyql, C_, F_);
    wconv_kernel<<<dim3(4, 48), 256>>>(Wyk, p_wykh, p_wykl, C_, F_);
    y_gemm<<<dim3(1, 8, 8), 256, GEMM_SMEM>>>(
        p_xgh, p_wyqh, p_wyql, p_wykh, p_wykl, p_ypart);

    // relative GEMMs (Qp/Kp band-trimmed: 20 of 32 tiles)
    rel_gemm<<<dim3(4, 4, 64), 256, GEMM_SMEM>>>(
        p_qh, p_kh, p_kl, p_QK, (const float*)0, P_, 1, 0, 1.0f);
    rel_gemm<<<dim3(20, 1, 64), 256, GEMM_SMEM>>>(
        p_qh, p_posh, p_posl, p_Qp, p_bias,           P2, 0, 1, 0.25f);
    rel_gemm<<<dim3(20, 1, 64), 256, GEMM_SMEM>>>(
        p_kh, p_posh, p_posl, p_Kp, p_bias + H_ * P2, P2, 0, 1, 0.25f);

    final_kernel<<<dim3(16, 16, 2), 256, SMEM_FINAL>>>(
        p_QK, p_Qp, p_Kp, p_ypart, Wout, bout, out);
}